// round 1
// baseline (speedup 1.0000x reference)
#include <cuda_runtime.h>
#include <math.h>

// ---------------- problem constants ----------------
constexpr int B_ = 2;
constexpr int S_ = 2048;
constexpr int D_ = 1024;
constexpr int H_ = 16;
constexpr int HD_ = 64;
constexpr int M_ = B_ * S_;          // 4096 rows
constexpr float LN_EPS = 1e-5f;

// ---------------- device scratch (no allocations allowed) ----------------
__device__ float g_q   [M_ * D_];
__device__ float g_k   [M_ * D_];
__device__ float g_v   [M_ * D_];
__device__ float g_attn[M_ * D_];
__device__ float g_h   [M_ * D_];
__device__ float g_h2  [M_ * D_];
__device__ float g_ff  [M_ * 4 * D_];

// ============================================================
// SGEMM: C[M,N] = A[M,K] @ W[K,N] (+ bias) (+ relu)
// 128x128 block tile, BK=16, 256 threads, 8x8 per thread.
// ============================================================
#define BM 128
#define BN 128
#define BK 16

__global__ __launch_bounds__(256, 2)
void sgemm_bias_kernel(const float* __restrict__ A, const float* __restrict__ W,
                       const float* __restrict__ bias, float* __restrict__ C,
                       int M, int N, int K, int relu)
{
    __shared__ float As[BK][BM + 4];   // stride 132 (mult of 4 -> float4 aligned)
    __shared__ float Bs[BK][BN + 4];

    const int tid = threadIdx.x;              // 0..255
    const int tx = tid & 15;                  // 0..15  (cols)
    const int ty = tid >> 4;                  // 0..15  (rows)
    const int block_row = blockIdx.y * BM;
    const int block_col = blockIdx.x * BN;

    float acc[8][8];
    #pragma unroll
    for (int r = 0; r < 8; r++)
        #pragma unroll
        for (int c = 0; c < 8; c++) acc[r][c] = 0.f;

    for (int k0 = 0; k0 < K; k0 += BK) {
        // load A tile (BM x BK) transposed into As[BK][BM]; 512 float4 / 256 thr = 2 each
        // load B tile (BK x BN) into Bs; 512 float4 / 256 thr = 2 each
        #pragma unroll
        for (int i = 0; i < 2; i++) {
            int lin = tid + i * 256;                  // 0..511
            int ar  = lin >> 2;                       // 0..127
            int ak  = (lin & 3) << 2;                 // 0,4,8,12
            float4 av = *(const float4*)&A[(size_t)(block_row + ar) * K + k0 + ak];
            As[ak + 0][ar] = av.x;
            As[ak + 1][ar] = av.y;
            As[ak + 2][ar] = av.z;
            As[ak + 3][ar] = av.w;
            int br  = lin >> 5;                       // 0..15
            int bc  = (lin & 31) << 2;                // 0..124
            *(float4*)&Bs[br][bc] =
                *(const float4*)&W[(size_t)(k0 + br) * N + block_col + bc];
        }
        __syncthreads();

        #pragma unroll
        for (int kk = 0; kk < BK; kk++) {
            float a[8], b[8];
            *(float4*)&a[0] = *(const float4*)&As[kk][ty * 8 + 0];
            *(float4*)&a[4] = *(const float4*)&As[kk][ty * 8 + 4];
            *(float4*)&b[0] = *(const float4*)&Bs[kk][tx * 8 + 0];
            *(float4*)&b[4] = *(const float4*)&Bs[kk][tx * 8 + 4];
            #pragma unroll
            for (int r = 0; r < 8; r++)
                #pragma unroll
                for (int c = 0; c < 8; c++)
                    acc[r][c] += a[r] * b[c];
        }
        __syncthreads();
    }

    // epilogue
    float bv[8];
    #pragma unroll
    for (int c = 0; c < 8; c++)
        bv[c] = bias ? bias[block_col + tx * 8 + c] : 0.f;

    #pragma unroll
    for (int r = 0; r < 8; r++) {
        int row = block_row + ty * 8 + r;
        float* crow = C + (size_t)row * N + block_col + tx * 8;
        float4 o0, o1;
        float v0 = acc[r][0] + bv[0], v1 = acc[r][1] + bv[1];
        float v2 = acc[r][2] + bv[2], v3 = acc[r][3] + bv[3];
        float v4 = acc[r][4] + bv[4], v5 = acc[r][5] + bv[5];
        float v6 = acc[r][6] + bv[6], v7 = acc[r][7] + bv[7];
        if (relu) {
            v0 = fmaxf(v0, 0.f); v1 = fmaxf(v1, 0.f); v2 = fmaxf(v2, 0.f); v3 = fmaxf(v3, 0.f);
            v4 = fmaxf(v4, 0.f); v5 = fmaxf(v5, 0.f); v6 = fmaxf(v6, 0.f); v7 = fmaxf(v7, 0.f);
        }
        o0.x = v0; o0.y = v1; o0.z = v2; o0.w = v3;
        o1.x = v4; o1.y = v5; o1.z = v6; o1.w = v7;
        *(float4*)&crow[0] = o0;
        *(float4*)&crow[4] = o1;
    }
}

// ============================================================
// Flash attention (fp32). One thread per query row.
// grid: (B*H, S/128), block: 128 threads.
// selfmode=1: s = s*scale; masked (==1) -> -3e38
// selfmode=0: masked (!=0) -> -1e9; then s *= scale     (matches reference order)
// ============================================================
#define QB 128
#define TS 64

__global__ __launch_bounds__(128, 3)
void flash_attn_kernel(const float* __restrict__ Q, const float* __restrict__ Kc,
                       const float* __restrict__ V, const int* __restrict__ mask,
                       float* __restrict__ O, int selfmode)
{
    __shared__ float Ks[TS][HD_];
    __shared__ float Vs[TS][HD_];

    const int bh = blockIdx.x;
    const int b  = bh / H_;
    const int h  = bh % H_;
    const int qi = blockIdx.y * QB + threadIdx.x;
    const float scale = 0.125f;     // 1/sqrt(64)

    float q[HD_], o[HD_];
    const float* qrow = Q + ((size_t)b * S_ + qi) * D_ + h * HD_;
    #pragma unroll
    for (int d4 = 0; d4 < 16; d4++) {
        float4 t = *(const float4*)&qrow[d4 * 4];
        q[4 * d4 + 0] = t.x; q[4 * d4 + 1] = t.y;
        q[4 * d4 + 2] = t.z; q[4 * d4 + 3] = t.w;
    }
    #pragma unroll
    for (int d = 0; d < HD_; d++) o[d] = 0.f;

    float mx = -INFINITY, l = 0.f;
    const int* mrow = mask + ((size_t)b * S_ + qi) * S_;

    for (int j0 = 0; j0 < S_; j0 += TS) {
        // cooperative tile load: 2*4096 floats = 2*1024 float4 / 128 thr = 8 each
        #pragma unroll
        for (int i = 0; i < 8; i++) {
            int lin = threadIdx.x + i * 128;     // 0..1023
            int r   = lin >> 4;                  // 0..63
            int c4  = (lin & 15) << 2;
            size_t gidx = ((size_t)b * S_ + j0 + r) * D_ + h * HD_ + c4;
            *(float4*)&Ks[r][c4] = *(const float4*)&Kc[gidx];
            *(float4*)&Vs[r][c4] = *(const float4*)&V[gidx];
        }
        __syncthreads();

        for (int j = 0; j < TS; j++) {
            float s0 = 0.f, s1 = 0.f, s2 = 0.f, s3 = 0.f;
            #pragma unroll
            for (int d4 = 0; d4 < 16; d4++) {
                float4 kk = *(const float4*)&Ks[j][d4 * 4];
                s0 += q[4 * d4 + 0] * kk.x;
                s1 += q[4 * d4 + 1] * kk.y;
                s2 += q[4 * d4 + 2] * kk.z;
                s3 += q[4 * d4 + 3] * kk.w;
            }
            float s = (s0 + s1) + (s2 + s3);
            int mv = __ldg(&mrow[j0 + j]);
            if (selfmode) {
                s *= scale;
                if (mv == 1) s = -3.0e38f;
            } else {
                if (mv != 0) s = -1e9f;
                s *= scale;
            }

            if (s > mx) {
                float corr = __expf(mx - s);
                mx = s;
                l = l * corr + 1.f;
                #pragma unroll
                for (int d4 = 0; d4 < 16; d4++) {
                    float4 vv = *(const float4*)&Vs[j][d4 * 4];
                    o[4 * d4 + 0] = o[4 * d4 + 0] * corr + vv.x;
                    o[4 * d4 + 1] = o[4 * d4 + 1] * corr + vv.y;
                    o[4 * d4 + 2] = o[4 * d4 + 2] * corr + vv.z;
                    o[4 * d4 + 3] = o[4 * d4 + 3] * corr + vv.w;
                }
            } else {
                float p = __expf(s - mx);
                l += p;
                #pragma unroll
                for (int d4 = 0; d4 < 16; d4++) {
                    float4 vv = *(const float4*)&Vs[j][d4 * 4];
                    o[4 * d4 + 0] += p * vv.x;
                    o[4 * d4 + 1] += p * vv.y;
                    o[4 * d4 + 2] += p * vv.z;
                    o[4 * d4 + 3] += p * vv.w;
                }
            }
        }
        __syncthreads();
    }

    float inv = 1.f / l;
    float* orow = O + ((size_t)b * S_ + qi) * D_ + h * HD_;
    #pragma unroll
    for (int d4 = 0; d4 < 16; d4++) {
        float4 t;
        t.x = o[4 * d4 + 0] * inv; t.y = o[4 * d4 + 1] * inv;
        t.z = o[4 * d4 + 2] * inv; t.w = o[4 * d4 + 3] * inv;
        *(float4*)&orow[d4 * 4] = t;
    }
}

// ============================================================
// LayerNorm over last dim (D=1024). One block (256 thr) per row.
// ============================================================
__global__ __launch_bounds__(256)
void layernorm_kernel(const float* __restrict__ X, const float* __restrict__ gm,
                      const float* __restrict__ bt, float* __restrict__ Y)
{
    const int row = blockIdx.x;
    const int t = threadIdx.x;
    const float* x = X + (size_t)row * D_;

    float4 xv = *(const float4*)&x[t * 4];
    float s  = xv.x + xv.y + xv.z + xv.w;
    float ss = xv.x * xv.x + xv.y * xv.y + xv.z * xv.z + xv.w * xv.w;

    #pragma unroll
    for (int off = 16; off > 0; off >>= 1) {
        s  += __shfl_xor_sync(0xffffffffu, s, off);
        ss += __shfl_xor_sync(0xffffffffu, ss, off);
    }
    __shared__ float sbuf[8], ssbuf[8];
    if ((t & 31) == 0) { sbuf[t >> 5] = s; ssbuf[t >> 5] = ss; }
    __syncthreads();
    float ts = 0.f, tss = 0.f;
    #pragma unroll
    for (int i = 0; i < 8; i++) { ts += sbuf[i]; tss += ssbuf[i]; }

    const float invD = 1.f / (float)D_;
    float mu  = ts * invD;
    float var = tss * invD - mu * mu;
    float inv = rsqrtf(var + LN_EPS);

    float4 gv = *(const float4*)&gm[t * 4];
    float4 bv = *(const float4*)&bt[t * 4];
    float4 out;
    out.x = (xv.x - mu) * inv * gv.x + bv.x;
    out.y = (xv.y - mu) * inv * gv.y + bv.y;
    out.z = (xv.z - mu) * inv * gv.z + bv.z;
    out.w = (xv.w - mu) * inv * gv.w + bv.w;
    *(float4*)&((Y + (size_t)row * D_)[t * 4]) = out;
}

// ============================================================
// launch plumbing
// ============================================================
static inline void run_gemm(const float* A, const float* W, const float* bias,
                            float* C, int M, int N, int K, int relu)
{
    dim3 grid(N / BN, M / BM), block(256);
    sgemm_bias_kernel<<<grid, block>>>(A, W, bias, C, M, N, K, relu);
}

extern "C" void kernel_launch(void* const* d_in, const int* in_sizes, int n_in,
                              void* d_out, int out_size)
{
    (void)in_sizes; (void)n_in; (void)out_size;
    const float* x    = (const float*)d_in[0];
    const float* y    = (const float*)d_in[1];
    const int*   mask = (const int*)  d_in[2];
    const float* qw   = (const float*)d_in[3];
    const float* qb   = (const float*)d_in[4];
    const float* kw   = (const float*)d_in[5];
    const float* kb   = (const float*)d_in[6];
    const float* vw   = (const float*)d_in[7];
    const float* vb   = (const float*)d_in[8];
    const float* ow   = (const float*)d_in[9];
    const float* ob   = (const float*)d_in[10];
    const float* f1w1 = (const float*)d_in[11];
    const float* f1b1 = (const float*)d_in[12];
    const float* f1w2 = (const float*)d_in[13];
    const float* f1b2 = (const float*)d_in[14];
    const float* ln1g = (const float*)d_in[15];
    const float* ln1b = (const float*)d_in[16];
    const float* cqw  = (const float*)d_in[17];
    const float* ckw  = (const float*)d_in[18];
    const float* cvw  = (const float*)d_in[19];
    const float* cow  = (const float*)d_in[20];
    const float* cob  = (const float*)d_in[21];
    const float* f2w1 = (const float*)d_in[22];
    const float* f2b1 = (const float*)d_in[23];
    const float* f2w2 = (const float*)d_in[24];
    const float* f2b2 = (const float*)d_in[25];
    const float* ln2g = (const float*)d_in[26];
    const float* ln2b = (const float*)d_in[27];
    float* out = (float*)d_out;

    float *q, *k, *v, *attn, *h, *h2, *ff;
    cudaGetSymbolAddress((void**)&q,    g_q);
    cudaGetSymbolAddress((void**)&k,    g_k);
    cudaGetSymbolAddress((void**)&v,    g_v);
    cudaGetSymbolAddress((void**)&attn, g_attn);
    cudaGetSymbolAddress((void**)&h,    g_h);
    cudaGetSymbolAddress((void**)&h2,   g_h2);
    cudaGetSymbolAddress((void**)&ff,   g_ff);

    dim3 fgrid(B_ * H_, S_ / QB), fblock(128);

    // ---- self-attention ----
    run_gemm(x, qw, qb, q, M_, D_, D_, 0);
    run_gemm(x, kw, kb, k, M_, D_, D_, 0);
    run_gemm(x, vw, vb, v, M_, D_, D_, 0);
    flash_attn_kernel<<<fgrid, fblock>>>(q, k, v, mask, attn, 1);
    run_gemm(attn, ow, ob, h, M_, D_, D_, 0);

    // ---- feedforward1 + norm1 ----
    run_gemm(h, f1w1, f1b1, ff, M_, 4 * D_, D_, 1);
    run_gemm(ff, f1w2, f1b2, h2, M_, D_, 4 * D_, 0);
    layernorm_kernel<<<M_, 256>>>(h2, ln1g, ln1b, h);

    // ---- cross-attention: q from h, k/v from y ----
    run_gemm(h, cqw, nullptr, q, M_, D_, D_, 0);
    run_gemm(y, ckw, nullptr, k, M_, D_, D_, 0);
    run_gemm(y, cvw, nullptr, v, M_, D_, D_, 0);
    flash_attn_kernel<<<fgrid, fblock>>>(q, k, v, mask, attn, 0);
    run_gemm(attn, cow, cob, h2, M_, D_, D_, 0);

    // ---- feedforward2 + norm2 ----
    run_gemm(h2, f2w1, f2b1, ff, M_, 4 * D_, D_, 1);
    run_gemm(ff, f2w2, f2b2, h2, M_, D_, 4 * D_, 0);
    layernorm_kernel<<<M_, 256>>>(h2, ln2g, ln2b, out);
}

// round 3
// speedup vs baseline: 1.3817x; 1.3817x over previous
#include <cuda_runtime.h>
#include <cuda_bf16.h>
#include <math.h>
#include <stdint.h>

// ---------------- problem constants ----------------
constexpr int B_ = 2;
constexpr int S_ = 2048;
constexpr int D_ = 1024;
constexpr int H_ = 16;
constexpr int HD_ = 64;
constexpr int M_ = B_ * S_;          // 4096 rows
constexpr float LN_EPS = 1e-5f;

// ---------------- device scratch (no allocations allowed) ----------------
__device__ float g_q   [M_ * D_];
__device__ float g_k   [M_ * D_];
__device__ float g_v   [M_ * D_];
__device__ float g_attn[M_ * D_];
__device__ float g_h   [M_ * D_];
__device__ float g_h2  [M_ * D_];
__device__ float g_ff  [M_ * 4 * D_];

// bf16 split buffers
constexpr size_t WT_ELEMS = 24ull * 1024 * 1024;    // all 12 transposed weights
__device__ __nv_bfloat16 g_wt_hi[WT_ELEMS];
__device__ __nv_bfloat16 g_wt_lo[WT_ELEMS];
__device__ __nv_bfloat16 g_a_hi[M_ * 4 * D_];
__device__ __nv_bfloat16 g_a_lo[M_ * 4 * D_];

// ---------------- PTX helpers (sm_80-class only; no 'a'-gated features) ----
__device__ __forceinline__ uint32_t smem_to_u32(const void* smem_ptr) {
    uint32_t addr;
    asm("{ .reg .u64 tmp; cvta.to.shared.u64 tmp, %1; cvt.u32.u64 %0, tmp; }"
        : "=r"(addr) : "l"(smem_ptr));
    return addr;
}
#define CP_ASYNC16(dst_u32, src_ptr) \
    asm volatile("cp.async.cg.shared.global [%0], [%1], 16;" \
        :: "r"(dst_u32), "l"(src_ptr))
#define CP_COMMIT() asm volatile("cp.async.commit_group;" ::: "memory")
#define CP_WAIT0()  asm volatile("cp.async.wait_group 0;" ::: "memory")
#define CP_WAIT1()  asm volatile("cp.async.wait_group 1;" ::: "memory")

#define LDSM_X4(r0, r1, r2, r3, addr) \
    asm volatile("ldmatrix.sync.aligned.m8n8.x4.shared.b16 {%0,%1,%2,%3}, [%4];" \
        : "=r"(r0), "=r"(r1), "=r"(r2), "=r"(r3) : "r"(addr))

#define MMA_BF16(c0, c1, c2, c3, a0, a1, a2, a3, b0, b1) \
    asm volatile("mma.sync.aligned.m16n8k16.row.col.f32.bf16.bf16.f32 " \
        "{%0,%1,%2,%3}, {%4,%5,%6,%7}, {%8,%9}, {%0,%1,%2,%3};" \
        : "+f"(c0), "+f"(c1), "+f"(c2), "+f"(c3) \
        : "r"(a0), "r"(a1), "r"(a2), "r"(a3), "r"(b0), "r"(b1))

// ============================================================
// HMMA split-bf16 GEMM: C[M,N] = (Ahi+Alo)[M,K] @ (Whi+Wlo)[N,K]^T
//   computes Ahi*Whi + Ahi*Wlo + Alo*Whi  (fp32 accumulate)
// CTA tile 128x128, BK=32, 256 threads (8 warps of 32x64), cp.async
// double buffer. Smem tile: 128 rows x 64B, XOR-swizzled 16B granules.
// ============================================================
constexpr int TILEB   = 8192;                // one 128x32 bf16 tile
constexpr int STAGEB  = 4 * TILEB;           // Ahi,Alo,Whi,Wlo
constexpr int GEMM_SMEM = 2 * STAGEB;        // 65536

__device__ __forceinline__ uint32_t swz(uint32_t row, uint32_t gk) {
    // byte offset within a tile; gk = 16B k-granule (0..3)
    return row * 64u + ((gk ^ ((row >> 1) & 3u)) << 4);
}

__global__ __launch_bounds__(256, 1)
void mma_gemm_kernel(const __nv_bfloat16* __restrict__ Ahi, const __nv_bfloat16* __restrict__ Alo,
                     const __nv_bfloat16* __restrict__ Whi, const __nv_bfloat16* __restrict__ Wlo,
                     const float* __restrict__ bias, float* __restrict__ C,
                     int M, int N, int K, int relu)
{
    extern __shared__ char smem[];
    const uint32_t su = smem_to_u32(smem);
    const int tid  = threadIdx.x;
    const int wid  = tid >> 5;
    const int lane = tid & 31;
    const int block_row = blockIdx.y * 128;
    const int block_col = blockIdx.x * 128;

    const __nv_bfloat16* basep[4] = { Ahi, Alo, Whi, Wlo };
    const int rowoff[4] = { block_row, block_row, block_col, block_col };

    // per-thread load slot: 8 chunks of 16B
    // chunk lin: tile = lin>>9, row = (lin&511)>>2, g = lin&3
    auto load_stage = [&](int p, int kt) {
        const int k0 = kt * 32;
        #pragma unroll
        for (int i = 0; i < 8; i++) {
            int lin  = tid + (i << 8);
            int tile = lin >> 9;
            int rem  = lin & 511;
            int row  = rem >> 2;
            int g    = rem & 3;
            const __nv_bfloat16* src =
                basep[tile] + (size_t)(rowoff[tile] + row) * K + k0 + g * 8;
            uint32_t dst = su + p * STAGEB + tile * TILEB + swz(row, g);
            CP_ASYNC16(dst, src);
        }
    };

    float c[2][8][4];
    #pragma unroll
    for (int s = 0; s < 2; s++)
        #pragma unroll
        for (int n = 0; n < 8; n++)
            #pragma unroll
            for (int i = 0; i < 4; i++) c[s][n][i] = 0.f;

    const int wm = (wid & 3) * 32;     // warp M offset within CTA tile
    const int wn = (wid >> 2) * 64;    // warp N offset

    // ldmatrix lane addressing
    const int a_row = (lane & 15);            // + wm + s*16
    const int a_gsel = (lane >> 4);           // 0/1 -> k granule +0/+1
    const int b_quad = lane >> 3;
    const int b_r    = lane & 7;
    const int b_noff = ((b_quad >> 1) << 3) + b_r;    // + wn + grp*16
    const int b_gsel = (b_quad & 1);

    const int KT = K >> 5;
    load_stage(0, 0);
    CP_COMMIT();

    for (int kt = 0; kt < KT; kt++) {
        if (kt + 1 < KT) { load_stage((kt + 1) & 1, kt + 1); CP_COMMIT(); CP_WAIT1(); }
        else             { CP_WAIT0(); }
        __syncthreads();

        const uint32_t stAhi = su + (kt & 1) * STAGEB;
        const uint32_t stAlo = stAhi + TILEB;
        const uint32_t stWhi = stAhi + 2 * TILEB;
        const uint32_t stWlo = stAhi + 3 * TILEB;

        #pragma unroll
        for (int kk = 0; kk < 2; kk++) {
            uint32_t ah[2][4], al[2][4], bh[8][2], bl[8][2];
            #pragma unroll
            for (int s = 0; s < 2; s++) {
                uint32_t ro = (uint32_t)(wm + s * 16 + a_row);
                uint32_t gk = (uint32_t)(kk * 2 + a_gsel);
                LDSM_X4(ah[s][0], ah[s][1], ah[s][2], ah[s][3], stAhi + swz(ro, gk));
                LDSM_X4(al[s][0], al[s][1], al[s][2], al[s][3], stAlo + swz(ro, gk));
            }
            #pragma unroll
            for (int grp = 0; grp < 4; grp++) {
                uint32_t ro = (uint32_t)(wn + grp * 16 + b_noff);
                uint32_t gk = (uint32_t)(kk * 2 + b_gsel);
                LDSM_X4(bh[2*grp][0], bh[2*grp][1], bh[2*grp+1][0], bh[2*grp+1][1],
                        stWhi + swz(ro, gk));
                LDSM_X4(bl[2*grp][0], bl[2*grp][1], bl[2*grp+1][0], bl[2*grp+1][1],
                        stWlo + swz(ro, gk));
            }
            // term 1: Ahi * Whi
            #pragma unroll
            for (int s = 0; s < 2; s++)
                #pragma unroll
                for (int n = 0; n < 8; n++)
                    MMA_BF16(c[s][n][0], c[s][n][1], c[s][n][2], c[s][n][3],
                             ah[s][0], ah[s][1], ah[s][2], ah[s][3],
                             bh[n][0], bh[n][1]);
            // term 2: Ahi * Wlo
            #pragma unroll
            for (int s = 0; s < 2; s++)
                #pragma unroll
                for (int n = 0; n < 8; n++)
                    MMA_BF16(c[s][n][0], c[s][n][1], c[s][n][2], c[s][n][3],
                             ah[s][0], ah[s][1], ah[s][2], ah[s][3],
                             bl[n][0], bl[n][1]);
            // term 3: Alo * Whi
            #pragma unroll
            for (int s = 0; s < 2; s++)
                #pragma unroll
                for (int n = 0; n < 8; n++)
                    MMA_BF16(c[s][n][0], c[s][n][1], c[s][n][2], c[s][n][3],
                             al[s][0], al[s][1], al[s][2], al[s][3],
                             bh[n][0], bh[n][1]);
        }
        __syncthreads();
    }

    // epilogue: c[s][n] covers rows (wm+s*16+g, +8), cols (wn+n*8+2*tig)
    const int gp  = lane >> 2;
    const int tig = lane & 3;
    #pragma unroll
    for (int s = 0; s < 2; s++) {
        const int r0 = block_row + wm + s * 16 + gp;
        #pragma unroll
        for (int n = 0; n < 8; n++) {
            const int col = block_col + wn + n * 8 + tig * 2;
            float b0 = bias ? __ldg(&bias[col])     : 0.f;
            float b1 = bias ? __ldg(&bias[col + 1]) : 0.f;
            float v0 = c[s][n][0] + b0, v1 = c[s][n][1] + b1;
            float v2 = c[s][n][2] + b0, v3 = c[s][n][3] + b1;
            if (relu) {
                v0 = fmaxf(v0, 0.f); v1 = fmaxf(v1, 0.f);
                v2 = fmaxf(v2, 0.f); v3 = fmaxf(v3, 0.f);
            }
            *(float2*)&C[(size_t)r0 * N + col]       = make_float2(v0, v1);
            *(float2*)&C[(size_t)(r0 + 8) * N + col] = make_float2(v2, v3);
        }
    }
}

// ============================================================
// prep: weight transpose + bf16 hi/lo split  W[K,N] -> Wt_hi/lo[N,K]
// ============================================================
__global__ __launch_bounds__(256)
void wsplit_kernel(const float* __restrict__ W, __nv_bfloat16* __restrict__ hi,
                   __nv_bfloat16* __restrict__ lo, int K, int N)
{
    __shared__ float t[32][33];
    const int tx = threadIdx.x, ty = threadIdx.y;      // 32 x 8
    const int n0 = blockIdx.x * 32, k0 = blockIdx.y * 32;
    #pragma unroll
    for (int r = 0; r < 4; r++)
        t[ty + r * 8][tx] = W[(size_t)(k0 + ty + r * 8) * N + n0 + tx];
    __syncthreads();
    #pragma unroll
    for (int r = 0; r < 4; r++) {
        float v = t[tx][ty + r * 8];
        size_t o = (size_t)(n0 + ty + r * 8) * K + k0 + tx;
        __nv_bfloat16 h = __float2bfloat16(v);
        hi[o] = h;
        lo[o] = __float2bfloat16(v - __bfloat162float(h));
    }
}

// prep: activation bf16 hi/lo split (elementwise)
__global__ __launch_bounds__(256)
void asplit_kernel(const float* __restrict__ A, __nv_bfloat16* __restrict__ hi,
                   __nv_bfloat16* __restrict__ lo, int n4)
{
    int i = blockIdx.x * 256 + threadIdx.x;
    if (i >= n4) return;
    float4 v = ((const float4*)A)[i];
    __nv_bfloat16 h0 = __float2bfloat16(v.x), h1 = __float2bfloat16(v.y);
    __nv_bfloat16 h2 = __float2bfloat16(v.z), h3 = __float2bfloat16(v.w);
    __nv_bfloat162* hp = (__nv_bfloat162*)hi;
    __nv_bfloat162* lp = (__nv_bfloat162*)lo;
    hp[2 * i + 0] = __nv_bfloat162(h0, h1);
    hp[2 * i + 1] = __nv_bfloat162(h2, h3);
    lp[2 * i + 0] = __nv_bfloat162(__float2bfloat16(v.x - __bfloat162float(h0)),
                                   __float2bfloat16(v.y - __bfloat162float(h1)));
    lp[2 * i + 1] = __nv_bfloat162(__float2bfloat16(v.z - __bfloat162float(h2)),
                                   __float2bfloat16(v.w - __bfloat162float(h3)));
}

// ============================================================
// Flash attention (fp32). One thread per query row. (unchanged, proven)
// ============================================================
#define QB 128
#define TS 64

__global__ __launch_bounds__(128, 3)
void flash_attn_kernel(const float* __restrict__ Q, const float* __restrict__ Kc,
                       const float* __restrict__ V, const int* __restrict__ mask,
                       float* __restrict__ O, int selfmode)
{
    __shared__ float Ks[TS][HD_];
    __shared__ float Vs[TS][HD_];

    const int bh = blockIdx.x;
    const int b  = bh / H_;
    const int h  = bh % H_;
    const int qi = blockIdx.y * QB + threadIdx.x;
    const float scale = 0.125f;

    float q[HD_], o[HD_];
    const float* qrow = Q + ((size_t)b * S_ + qi) * D_ + h * HD_;
    #pragma unroll
    for (int d4 = 0; d4 < 16; d4++) {
        float4 t = *(const float4*)&qrow[d4 * 4];
        q[4 * d4 + 0] = t.x; q[4 * d4 + 1] = t.y;
        q[4 * d4 + 2] = t.z; q[4 * d4 + 3] = t.w;
    }
    #pragma unroll
    for (int d = 0; d < HD_; d++) o[d] = 0.f;

    float mx = -INFINITY, l = 0.f;
    const int* mrow = mask + ((size_t)b * S_ + qi) * S_;

    for (int j0 = 0; j0 < S_; j0 += TS) {
        #pragma unroll
        for (int i = 0; i < 8; i++) {
            int lin = threadIdx.x + i * 128;
            int r   = lin >> 4;
            int c4  = (lin & 15) << 2;
            size_t gidx = ((size_t)b * S_ + j0 + r) * D_ + h * HD_ + c4;
            *(float4*)&Ks[r][c4] = *(const float4*)&Kc[gidx];
            *(float4*)&Vs[r][c4] = *(const float4*)&V[gidx];
        }
        __syncthreads();

        for (int j = 0; j < TS; j++) {
            float s0 = 0.f, s1 = 0.f, s2 = 0.f, s3 = 0.f;
            #pragma unroll
            for (int d4 = 0; d4 < 16; d4++) {
                float4 kk = *(const float4*)&Ks[j][d4 * 4];
                s0 += q[4 * d4 + 0] * kk.x;
                s1 += q[4 * d4 + 1] * kk.y;
                s2 += q[4 * d4 + 2] * kk.z;
                s3 += q[4 * d4 + 3] * kk.w;
            }
            float s = (s0 + s1) + (s2 + s3);
            int mv = __ldg(&mrow[j0 + j]);
            if (selfmode) {
                s *= scale;
                if (mv == 1) s = -3.0e38f;
            } else {
                if (mv != 0) s = -1e9f;
                s *= scale;
            }

            if (s > mx) {
                float corr = __expf(mx - s);
                mx = s;
                l = l * corr + 1.f;
                #pragma unroll
                for (int d4 = 0; d4 < 16; d4++) {
                    float4 vv = *(const float4*)&Vs[j][d4 * 4];
                    o[4 * d4 + 0] = o[4 * d4 + 0] * corr + vv.x;
                    o[4 * d4 + 1] = o[4 * d4 + 1] * corr + vv.y;
                    o[4 * d4 + 2] = o[4 * d4 + 2] * corr + vv.z;
                    o[4 * d4 + 3] = o[4 * d4 + 3] * corr + vv.w;
                }
            } else {
                float p = __expf(s - mx);
                l += p;
                #pragma unroll
                for (int d4 = 0; d4 < 16; d4++) {
                    float4 vv = *(const float4*)&Vs[j][d4 * 4];
                    o[4 * d4 + 0] += p * vv.x;
                    o[4 * d4 + 1] += p * vv.y;
                    o[4 * d4 + 2] += p * vv.z;
                    o[4 * d4 + 3] += p * vv.w;
                }
            }
        }
        __syncthreads();
    }

    float inv = 1.f / l;
    float* orow = O + ((size_t)b * S_ + qi) * D_ + h * HD_;
    #pragma unroll
    for (int d4 = 0; d4 < 16; d4++) {
        float4 t;
        t.x = o[4 * d4 + 0] * inv; t.y = o[4 * d4 + 1] * inv;
        t.z = o[4 * d4 + 2] * inv; t.w = o[4 * d4 + 3] * inv;
        *(float4*)&orow[d4 * 4] = t;
    }
}

// ============================================================
// LayerNorm (unchanged)
// ============================================================
__global__ __launch_bounds__(256)
void layernorm_kernel(const float* __restrict__ X, const float* __restrict__ gm,
                      const float* __restrict__ bt, float* __restrict__ Y)
{
    const int row = blockIdx.x;
    const int t = threadIdx.x;
    const float* x = X + (size_t)row * D_;

    float4 xv = *(const float4*)&x[t * 4];
    float s  = xv.x + xv.y + xv.z + xv.w;
    float ss = xv.x * xv.x + xv.y * xv.y + xv.z * xv.z + xv.w * xv.w;

    #pragma unroll
    for (int off = 16; off > 0; off >>= 1) {
        s  += __shfl_xor_sync(0xffffffffu, s, off);
        ss += __shfl_xor_sync(0xffffffffu, ss, off);
    }
    __shared__ float sbuf[8], ssbuf[8];
    if ((t & 31) == 0) { sbuf[t >> 5] = s; ssbuf[t >> 5] = ss; }
    __syncthreads();
    float ts = 0.f, tss = 0.f;
    #pragma unroll
    for (int i = 0; i < 8; i++) { ts += sbuf[i]; tss += ssbuf[i]; }

    const float invD = 1.f / (float)D_;
    float mu  = ts * invD;
    float var = tss * invD - mu * mu;
    float inv = rsqrtf(var + LN_EPS);

    float4 gv = *(const float4*)&gm[t * 4];
    float4 bv = *(const float4*)&bt[t * 4];
    float4 out;
    out.x = (xv.x - mu) * inv * gv.x + bv.x;
    out.y = (xv.y - mu) * inv * gv.y + bv.y;
    out.z = (xv.z - mu) * inv * gv.z + bv.z;
    out.w = (xv.w - mu) * inv * gv.w + bv.w;
    *(float4*)&((Y + (size_t)row * D_)[t * 4]) = out;
}

// ============================================================
// launch plumbing
// ============================================================
constexpr size_t MB1 = 1024ull * 1024ull;
constexpr size_t OFF_QW = 0,       OFF_KW = 1*MB1,  OFF_VW = 2*MB1,  OFF_OW = 3*MB1;
constexpr size_t OFF_F1W1 = 4*MB1, OFF_F1W2 = 8*MB1;
constexpr size_t OFF_CQW = 12*MB1, OFF_CKW = 13*MB1, OFF_CVW = 14*MB1, OFF_COW = 15*MB1;
constexpr size_t OFF_F2W1 = 16*MB1, OFF_F2W2 = 20*MB1;

struct Ctx {
    __nv_bfloat16 *wt_hi, *wt_lo, *a_hi, *a_lo;
};

static inline void run_wsplit(const float* W, __nv_bfloat16* hi, __nv_bfloat16* lo,
                              int K, int N) {
    dim3 grid(N / 32, K / 32), block(32, 8);
    wsplit_kernel<<<grid, block>>>(W, hi, lo, K, N);
}
static inline void run_asplit(const float* A, const Ctx& c, size_t elems) {
    int n4 = (int)(elems / 4);
    asplit_kernel<<<(n4 + 255) / 256, 256>>>(A, c.a_hi, c.a_lo, n4);
}
static inline void run_tcgemm(const Ctx& c, size_t woff, const float* bias, float* C,
                              int M, int N, int K, int relu) {
    dim3 grid(N / 128, M / 128), block(256);
    mma_gemm_kernel<<<grid, block, GEMM_SMEM>>>(
        c.a_hi, c.a_lo, c.wt_hi + woff, c.wt_lo + woff, bias, C, M, N, K, relu);
}

extern "C" void kernel_launch(void* const* d_in, const int* in_sizes, int n_in,
                              void* d_out, int out_size)
{
    (void)in_sizes; (void)n_in; (void)out_size;
    const float* x    = (const float*)d_in[0];
    const float* y    = (const float*)d_in[1];
    const int*   mask = (const int*)  d_in[2];
    const float* qw   = (const float*)d_in[3];
    const float* qb   = (const float*)d_in[4];
    const float* kw   = (const float*)d_in[5];
    const float* kb   = (const float*)d_in[6];
    const float* vw   = (const float*)d_in[7];
    const float* vb   = (const float*)d_in[8];
    const float* ow   = (const float*)d_in[9];
    const float* ob   = (const float*)d_in[10];
    const float* f1w1 = (const float*)d_in[11];
    const float* f1b1 = (const float*)d_in[12];
    const float* f1w2 = (const float*)d_in[13];
    const float* f1b2 = (const float*)d_in[14];
    const float* ln1g = (const float*)d_in[15];
    const float* ln1b = (const float*)d_in[16];
    const float* cqw  = (const float*)d_in[17];
    const float* ckw  = (const float*)d_in[18];
    const float* cvw  = (const float*)d_in[19];
    const float* cow  = (const float*)d_in[20];
    const float* cob  = (const float*)d_in[21];
    const float* f2w1 = (const float*)d_in[22];
    const float* f2b1 = (const float*)d_in[23];
    const float* f2w2 = (const float*)d_in[24];
    const float* f2b2 = (const float*)d_in[25];
    const float* ln2g = (const float*)d_in[26];
    const float* ln2b = (const float*)d_in[27];
    float* out = (float*)d_out;

    float *q, *k, *v, *attn, *h, *h2, *ff;
    cudaGetSymbolAddress((void**)&q,    g_q);
    cudaGetSymbolAddress((void**)&k,    g_k);
    cudaGetSymbolAddress((void**)&v,    g_v);
    cudaGetSymbolAddress((void**)&attn, g_attn);
    cudaGetSymbolAddress((void**)&h,    g_h);
    cudaGetSymbolAddress((void**)&h2,   g_h2);
    cudaGetSymbolAddress((void**)&ff,   g_ff);

    Ctx c;
    cudaGetSymbolAddress((void**)&c.wt_hi, g_wt_hi);
    cudaGetSymbolAddress((void**)&c.wt_lo, g_wt_lo);
    cudaGetSymbolAddress((void**)&c.a_hi,  g_a_hi);
    cudaGetSymbolAddress((void**)&c.a_lo,  g_a_lo);

    cudaFuncSetAttribute(mma_gemm_kernel,
                         cudaFuncAttributeMaxDynamicSharedMemorySize, GEMM_SMEM);

    // ---- weight prep (transpose + split) ----
    run_wsplit(qw,   c.wt_hi + OFF_QW,   c.wt_lo + OFF_QW,   D_, D_);
    run_wsplit(kw,   c.wt_hi + OFF_KW,   c.wt_lo + OFF_KW,   D_, D_);
    run_wsplit(vw,   c.wt_hi + OFF_VW,   c.wt_lo + OFF_VW,   D_, D_);
    run_wsplit(ow,   c.wt_hi + OFF_OW,   c.wt_lo + OFF_OW,   D_, D_);
    run_wsplit(f1w1, c.wt_hi + OFF_F1W1, c.wt_lo + OFF_F1W1, D_, 4 * D_);
    run_wsplit(f1w2, c.wt_hi + OFF_F1W2, c.wt_lo + OFF_F1W2, 4 * D_, D_);
    run_wsplit(cqw,  c.wt_hi + OFF_CQW,  c.wt_lo + OFF_CQW,  D_, D_);
    run_wsplit(ckw,  c.wt_hi + OFF_CKW,  c.wt_lo + OFF_CKW,  D_, D_);
    run_wsplit(cvw,  c.wt_hi + OFF_CVW,  c.wt_lo + OFF_CVW,  D_, D_);
    run_wsplit(cow,  c.wt_hi + OFF_COW,  c.wt_lo + OFF_COW,  D_, D_);
    run_wsplit(f2w1, c.wt_hi + OFF_F2W1, c.wt_lo + OFF_F2W1, D_, 4 * D_);
    run_wsplit(f2w2, c.wt_hi + OFF_F2W2, c.wt_lo + OFF_F2W2, 4 * D_, D_);

    dim3 fgrid(B_ * H_, S_ / QB), fblock(128);

    // ---- self-attention ----
    run_asplit(x, c, (size_t)M_ * D_);
    run_tcgemm(c, OFF_QW, qb, q, M_, D_, D_, 0);
    run_tcgemm(c, OFF_KW, kb, k, M_, D_, D_, 0);
    run_tcgemm(c, OFF_VW, vb, v, M_, D_, D_, 0);
    flash_attn_kernel<<<fgrid, fblock>>>(q, k, v, mask, attn, 1);
    run_asplit(attn, c, (size_t)M_ * D_);
    run_tcgemm(c, OFF_OW, ob, h, M_, D_, D_, 0);

    // ---- feedforward1 + norm1 ----
    run_asplit(h, c, (size_t)M_ * D_);
    run_tcgemm(c, OFF_F1W1, f1b1, ff, M_, 4 * D_, D_, 1);
    run_asplit(ff, c, (size_t)M_ * 4 * D_);
    run_tcgemm(c, OFF_F1W2, f1b2, h2, M_, D_, 4 * D_, 0);
    layernorm_kernel<<<M_, 256>>>(h2, ln1g, ln1b, h);

    // ---- cross-attention: q from h, k/v from y ----
    run_asplit(h, c, (size_t)M_ * D_);
    run_tcgemm(c, OFF_CQW, nullptr, q, M_, D_, D_, 0);
    run_asplit(y, c, (size_t)M_ * D_);
    run_tcgemm(c, OFF_CKW, nullptr, k, M_, D_, D_, 0);
    run_tcgemm(c, OFF_CVW, nullptr, v, M_, D_, D_, 0);
    flash_attn_kernel<<<fgrid, fblock>>>(q, k, v, mask, attn, 0);
    run_asplit(attn, c, (size_t)M_ * D_);
    run_tcgemm(c, OFF_COW, cob, h2, M_, D_, D_, 0);

    // ---- feedforward2 + norm2 ----
    run_asplit(h2, c, (size_t)M_ * D_);
    run_tcgemm(c, OFF_F2W1, f2b1, ff, M_, 4 * D_, D_, 1);
    run_asplit(ff, c, (size_t)M_ * 4 * D_);
    run_tcgemm(c, OFF_F2W2, f2b2, h2, M_, D_, 4 * D_, 0);
    layernorm_kernel<<<M_, 256>>>(h2, ln2g, ln2b, out);
}

// round 4
// speedup vs baseline: 3.6817x; 2.6646x over previous
#include <cuda_runtime.h>
#include <cuda_bf16.h>
#include <math.h>
#include <stdint.h>

// ---------------- problem constants ----------------
constexpr int B_ = 2;
constexpr int S_ = 2048;
constexpr int D_ = 1024;
constexpr int H_ = 16;
constexpr int HD_ = 64;
constexpr int M_ = B_ * S_;          // 4096 rows
constexpr float LN_EPS = 1e-5f;

// ---------------- device scratch (no allocations allowed) ----------------
__device__ float g_h2 [M_ * D_];     // fp32 pre-LN buffer

constexpr size_t WT_ELEMS = 24ull * 1024 * 1024;    // all 12 transposed weights
__device__ __nv_bfloat16 g_wt_hi[WT_ELEMS];
__device__ __nv_bfloat16 g_wt_lo[WT_ELEMS];
// activation split ping-pong buffers
__device__ __nv_bfloat16 g_a_hi[M_ * 4 * D_];
__device__ __nv_bfloat16 g_a_lo[M_ * 4 * D_];
__device__ __nv_bfloat16 g_b_hi[M_ * 4 * D_];
__device__ __nv_bfloat16 g_b_lo[M_ * 4 * D_];
// q/k/v split buffers
__device__ __nv_bfloat16 g_qhi[M_ * D_], g_qlo[M_ * D_];
__device__ __nv_bfloat16 g_khi[M_ * D_], g_klo[M_ * D_];
__device__ __nv_bfloat16 g_vhi[M_ * D_], g_vlo[M_ * D_];

// ---------------- PTX helpers (sm_80-class only) ----------------
__device__ __forceinline__ uint32_t smem_to_u32(const void* smem_ptr) {
    uint32_t addr;
    asm("{ .reg .u64 tmp; cvta.to.shared.u64 tmp, %1; cvt.u32.u64 %0, tmp; }"
        : "=r"(addr) : "l"(smem_ptr));
    return addr;
}
#define CP_ASYNC16(dst_u32, src_ptr) \
    asm volatile("cp.async.cg.shared.global [%0], [%1], 16;" \
        :: "r"(dst_u32), "l"(src_ptr))
#define CP_COMMIT() asm volatile("cp.async.commit_group;" ::: "memory")
#define CP_WAIT0()  asm volatile("cp.async.wait_group 0;" ::: "memory")
#define CP_WAIT1()  asm volatile("cp.async.wait_group 1;" ::: "memory")

#define LDSM_X4(r0, r1, r2, r3, addr) \
    asm volatile("ldmatrix.sync.aligned.m8n8.x4.shared.b16 {%0,%1,%2,%3}, [%4];" \
        : "=r"(r0), "=r"(r1), "=r"(r2), "=r"(r3) : "r"(addr))
#define LDSM_X4_T(r0, r1, r2, r3, addr) \
    asm volatile("ldmatrix.sync.aligned.m8n8.x4.trans.shared.b16 {%0,%1,%2,%3}, [%4];" \
        : "=r"(r0), "=r"(r1), "=r"(r2), "=r"(r3) : "r"(addr))

#define MMA_BF16(c0, c1, c2, c3, a0, a1, a2, a3, b0, b1) \
    asm volatile("mma.sync.aligned.m16n8k16.row.col.f32.bf16.bf16.f32 " \
        "{%0,%1,%2,%3}, {%4,%5,%6,%7}, {%8,%9}, {%0,%1,%2,%3};" \
        : "+f"(c0), "+f"(c1), "+f"(c2), "+f"(c3) \
        : "r"(a0), "r"(a1), "r"(a2), "r"(a3), "r"(b0), "r"(b1))

__device__ __forceinline__ uint32_t bf2u(__nv_bfloat162 v) {
    return *reinterpret_cast<uint32_t*>(&v);
}

// ============================================================
// HMMA split-bf16 GEMM: C = (Ahi+Alo)[M,K] @ (Whi+Wlo)[N,K]^T
// outmode 0: fp32 Cf;  outmode 1: bf16 hi/lo split to Chi/Clo
// ============================================================
constexpr int TILEB   = 8192;                // one 128x32 bf16 tile
constexpr int STAGEB  = 4 * TILEB;           // Ahi,Alo,Whi,Wlo
constexpr int GEMM_SMEM = 2 * STAGEB;        // 65536

__device__ __forceinline__ uint32_t swz(uint32_t row, uint32_t gk) {
    return row * 64u + ((gk ^ ((row >> 1) & 3u)) << 4);
}

__global__ __launch_bounds__(256, 1)
void mma_gemm_kernel(const __nv_bfloat16* __restrict__ Ahi, const __nv_bfloat16* __restrict__ Alo,
                     const __nv_bfloat16* __restrict__ Whi, const __nv_bfloat16* __restrict__ Wlo,
                     const float* __restrict__ bias, float* __restrict__ Cf,
                     __nv_bfloat16* __restrict__ Chi, __nv_bfloat16* __restrict__ Clo,
                     int M, int N, int K, int relu, int outmode)
{
    extern __shared__ char smem[];
    const uint32_t su = smem_to_u32(smem);
    const int tid  = threadIdx.x;
    const int wid  = tid >> 5;
    const int lane = tid & 31;
    const int block_row = blockIdx.y * 128;
    const int block_col = blockIdx.x * 128;

    const __nv_bfloat16* basep[4] = { Ahi, Alo, Whi, Wlo };
    const int rowoff[4] = { block_row, block_row, block_col, block_col };

    auto load_stage = [&](int p, int kt) {
        const int k0 = kt * 32;
        #pragma unroll
        for (int i = 0; i < 8; i++) {
            int lin  = tid + (i << 8);
            int tile = lin >> 9;
            int rem  = lin & 511;
            int row  = rem >> 2;
            int g    = rem & 3;
            const __nv_bfloat16* src =
                basep[tile] + (size_t)(rowoff[tile] + row) * K + k0 + g * 8;
            uint32_t dst = su + p * STAGEB + tile * TILEB + swz(row, g);
            CP_ASYNC16(dst, src);
        }
    };

    float c[2][8][4];
    #pragma unroll
    for (int s = 0; s < 2; s++)
        #pragma unroll
        for (int n = 0; n < 8; n++)
            #pragma unroll
            for (int i = 0; i < 4; i++) c[s][n][i] = 0.f;

    const int wm = (wid & 3) * 32;
    const int wn = (wid >> 2) * 64;

    const int a_row  = (lane & 15);
    const int a_gsel = (lane >> 4);
    const int b_noff = ((lane >> 4) << 3) + (lane & 7);
    const int b_gsel = (lane >> 3) & 1;

    const int KT = K >> 5;
    load_stage(0, 0);
    CP_COMMIT();

    for (int kt = 0; kt < KT; kt++) {
        if (kt + 1 < KT) { load_stage((kt + 1) & 1, kt + 1); CP_COMMIT(); CP_WAIT1(); }
        else             { CP_WAIT0(); }
        __syncthreads();

        const uint32_t stAhi = su + (kt & 1) * STAGEB;
        const uint32_t stAlo = stAhi + TILEB;
        const uint32_t stWhi = stAhi + 2 * TILEB;
        const uint32_t stWlo = stAhi + 3 * TILEB;

        #pragma unroll
        for (int kk = 0; kk < 2; kk++) {
            uint32_t ah[2][4], al[2][4], bh[8][2], bl[8][2];
            #pragma unroll
            for (int s = 0; s < 2; s++) {
                uint32_t ro = (uint32_t)(wm + s * 16 + a_row);
                uint32_t gk = (uint32_t)(kk * 2 + a_gsel);
                LDSM_X4(ah[s][0], ah[s][1], ah[s][2], ah[s][3], stAhi + swz(ro, gk));
                LDSM_X4(al[s][0], al[s][1], al[s][2], al[s][3], stAlo + swz(ro, gk));
            }
            #pragma unroll
            for (int grp = 0; grp < 4; grp++) {
                uint32_t ro = (uint32_t)(wn + grp * 16 + b_noff);
                uint32_t gk = (uint32_t)(kk * 2 + b_gsel);
                LDSM_X4(bh[2*grp][0], bh[2*grp][1], bh[2*grp+1][0], bh[2*grp+1][1],
                        stWhi + swz(ro, gk));
                LDSM_X4(bl[2*grp][0], bl[2*grp][1], bl[2*grp+1][0], bl[2*grp+1][1],
                        stWlo + swz(ro, gk));
            }
            #pragma unroll
            for (int s = 0; s < 2; s++)
                #pragma unroll
                for (int n = 0; n < 8; n++)
                    MMA_BF16(c[s][n][0], c[s][n][1], c[s][n][2], c[s][n][3],
                             ah[s][0], ah[s][1], ah[s][2], ah[s][3],
                             bh[n][0], bh[n][1]);
            #pragma unroll
            for (int s = 0; s < 2; s++)
                #pragma unroll
                for (int n = 0; n < 8; n++)
                    MMA_BF16(c[s][n][0], c[s][n][1], c[s][n][2], c[s][n][3],
                             ah[s][0], ah[s][1], ah[s][2], ah[s][3],
                             bl[n][0], bl[n][1]);
            #pragma unroll
            for (int s = 0; s < 2; s++)
                #pragma unroll
                for (int n = 0; n < 8; n++)
                    MMA_BF16(c[s][n][0], c[s][n][1], c[s][n][2], c[s][n][3],
                             al[s][0], al[s][1], al[s][2], al[s][3],
                             bh[n][0], bh[n][1]);
        }
        __syncthreads();
    }

    const int gp  = lane >> 2;
    const int tig = lane & 3;
    #pragma unroll
    for (int s = 0; s < 2; s++) {
        const int r0 = block_row + wm + s * 16 + gp;
        #pragma unroll
        for (int n = 0; n < 8; n++) {
            const int col = block_col + wn + n * 8 + tig * 2;
            float b0 = bias ? __ldg(&bias[col])     : 0.f;
            float b1 = bias ? __ldg(&bias[col + 1]) : 0.f;
            float v0 = c[s][n][0] + b0, v1 = c[s][n][1] + b1;
            float v2 = c[s][n][2] + b0, v3 = c[s][n][3] + b1;
            if (relu) {
                v0 = fmaxf(v0, 0.f); v1 = fmaxf(v1, 0.f);
                v2 = fmaxf(v2, 0.f); v3 = fmaxf(v3, 0.f);
            }
            if (outmode == 0) {
                *(float2*)&Cf[(size_t)r0 * N + col]       = make_float2(v0, v1);
                *(float2*)&Cf[(size_t)(r0 + 8) * N + col] = make_float2(v2, v3);
            } else {
                __nv_bfloat162 h01 = __float22bfloat162_rn(make_float2(v0, v1));
                __nv_bfloat162 h23 = __float22bfloat162_rn(make_float2(v2, v3));
                __nv_bfloat162 l01 = __float22bfloat162_rn(make_float2(
                    v0 - __bfloat162float(h01.x), v1 - __bfloat162float(h01.y)));
                __nv_bfloat162 l23 = __float22bfloat162_rn(make_float2(
                    v2 - __bfloat162float(h23.x), v3 - __bfloat162float(h23.y)));
                *(__nv_bfloat162*)&Chi[(size_t)r0 * N + col]       = h01;
                *(__nv_bfloat162*)&Chi[(size_t)(r0 + 8) * N + col] = h23;
                *(__nv_bfloat162*)&Clo[(size_t)r0 * N + col]       = l01;
                *(__nv_bfloat162*)&Clo[(size_t)(r0 + 8) * N + col] = l23;
            }
        }
    }
}

// ============================================================
// MMA flash attention. CTA: 64 q-rows, 4 warps (16 rows each), Bc=64.
// Scores: 3-term split bf16 MMA; softmax fp32; PV: 3-term split.
// Inputs/outputs are bf16 hi/lo split buffers laid out [b*S+r][D].
// ============================================================
constexpr int ATT_KHI = 0;
constexpr int ATT_KLO = 8192;
constexpr int ATT_VHI = 16384;
constexpr int ATT_VLO = 24576;
constexpr int ATT_MSK = 32768;               // 64 rows x 288 bytes
constexpr int ATT_SMEM = 32768 + 64 * 288;   // 51200

__device__ __forceinline__ uint32_t offKV(uint32_t row, uint32_t g) {
    return row * 128u + ((g ^ (row & 7u)) << 4);
}

__global__ __launch_bounds__(128)
void mma_attn_kernel(const __nv_bfloat16* __restrict__ Qhi, const __nv_bfloat16* __restrict__ Qlo,
                     const __nv_bfloat16* __restrict__ Khi, const __nv_bfloat16* __restrict__ Klo,
                     const __nv_bfloat16* __restrict__ Vhi, const __nv_bfloat16* __restrict__ Vlo,
                     const int* __restrict__ mask,
                     __nv_bfloat16* __restrict__ Ohi, __nv_bfloat16* __restrict__ Olo,
                     int selfmode)
{
    extern __shared__ char smem[];
    const uint32_t su = smem_to_u32(smem);
    const int tid = threadIdx.x, wid = tid >> 5, lane = tid & 31;
    const int b = blockIdx.x >> 4, h = blockIdx.x & 15;
    const int q0 = blockIdx.y * 64;

    // ---- stage Q tiles through smem, build A fragments ----
    #pragma unroll
    for (int i = 0; i < 8; i++) {
        int lin = tid + (i << 7);
        int t = lin >> 9, rem = lin & 511, row = rem >> 3, g = rem & 7;
        const __nv_bfloat16* src = (t ? Qlo : Qhi) +
            ((size_t)b * S_ + q0 + row) * D_ + h * 64 + g * 8;
        CP_ASYNC16(su + t * 8192 + offKV(row, g), src);
    }
    CP_COMMIT(); CP_WAIT0(); __syncthreads();

    uint32_t qa_hi[4][4], qa_lo[4][4];
    {
        const uint32_t arow = (uint32_t)(wid * 16 + (lane & 15));
        const uint32_t ag = (uint32_t)(lane >> 4);
        #pragma unroll
        for (int kk = 0; kk < 4; kk++) {
            LDSM_X4(qa_hi[kk][0], qa_hi[kk][1], qa_hi[kk][2], qa_hi[kk][3],
                    su + offKV(arow, kk * 2 + ag));
            LDSM_X4(qa_lo[kk][0], qa_lo[kk][1], qa_lo[kk][2], qa_lo[kk][3],
                    su + 8192 + offKV(arow, kk * 2 + ag));
        }
    }
    __syncthreads();

    float o[8][4];
    #pragma unroll
    for (int n = 0; n < 8; n++)
        #pragma unroll
        for (int i = 0; i < 4; i++) o[n][i] = 0.f;
    float m0 = -INFINITY, m1 = -INFINITY, l0 = 0.f, l1 = 0.f;
    const float scale = 0.125f;
    const float bigneg = selfmode ? -3.0e38f : -1.25e8f;

    const int b_noff = ((lane >> 4) << 3) + (lane & 7);
    const int b_gsel = (lane >> 3) & 1;
    const int mr0 = wid * 16 + (lane >> 2);
    const int mcolb = (2 * (lane & 3)) * 4;

    const __nv_bfloat16* kvp[4] = { Khi, Klo, Vhi, Vlo };

    for (int jt = 0; jt < 32; jt++) {
        const int j0 = jt * 64;
        // load K/V tiles
        #pragma unroll
        for (int i = 0; i < 16; i++) {
            int lin = tid + (i << 7);
            int t = lin >> 9, rem = lin & 511, row = rem >> 3, g = rem & 7;
            CP_ASYNC16(su + t * 8192 + offKV(row, g),
                       kvp[t] + ((size_t)b * S_ + j0 + row) * D_ + h * 64 + g * 8);
        }
        // load mask tile (q0..q0+63) x (j0..j0+63)
        #pragma unroll
        for (int i = 0; i < 8; i++) {
            int lin = tid + (i << 7);
            int row = lin >> 4, ch = lin & 15;
            CP_ASYNC16(su + ATT_MSK + row * 288 + ch * 16,
                       mask + ((size_t)b * S_ + q0 + row) * S_ + j0 + ch * 4);
        }
        CP_COMMIT(); CP_WAIT0(); __syncthreads();

        // ---- S = Q K^T (3-term) ----
        float sc[8][4];
        #pragma unroll
        for (int n = 0; n < 8; n++)
            #pragma unroll
            for (int i = 0; i < 4; i++) sc[n][i] = 0.f;

        #pragma unroll
        for (int kk = 0; kk < 4; kk++) {
            uint32_t kbh[8][2], kbl[8][2];
            #pragma unroll
            for (int grp = 0; grp < 4; grp++) {
                uint32_t ro = (uint32_t)(grp * 16 + b_noff);
                uint32_t gd = (uint32_t)(kk * 2 + b_gsel);
                LDSM_X4(kbh[2*grp][0], kbh[2*grp][1], kbh[2*grp+1][0], kbh[2*grp+1][1],
                        su + ATT_KHI + offKV(ro, gd));
                LDSM_X4(kbl[2*grp][0], kbl[2*grp][1], kbl[2*grp+1][0], kbl[2*grp+1][1],
                        su + ATT_KLO + offKV(ro, gd));
            }
            #pragma unroll
            for (int n = 0; n < 8; n++)
                MMA_BF16(sc[n][0], sc[n][1], sc[n][2], sc[n][3],
                         qa_hi[kk][0], qa_hi[kk][1], qa_hi[kk][2], qa_hi[kk][3],
                         kbh[n][0], kbh[n][1]);
            #pragma unroll
            for (int n = 0; n < 8; n++)
                MMA_BF16(sc[n][0], sc[n][1], sc[n][2], sc[n][3],
                         qa_hi[kk][0], qa_hi[kk][1], qa_hi[kk][2], qa_hi[kk][3],
                         kbl[n][0], kbl[n][1]);
            #pragma unroll
            for (int n = 0; n < 8; n++)
                MMA_BF16(sc[n][0], sc[n][1], sc[n][2], sc[n][3],
                         qa_lo[kk][0], qa_lo[kk][1], qa_lo[kk][2], qa_lo[kk][3],
                         kbh[n][0], kbh[n][1]);
        }

        // ---- mask + scale ----
        #pragma unroll
        for (int n = 0; n < 8; n++) {
            int cb = n * 32 + mcolb;
            int2 mk0 = *(const int2*)(smem + ATT_MSK + mr0 * 288 + cb);
            int2 mk1 = *(const int2*)(smem + ATT_MSK + (mr0 + 8) * 288 + cb);
            bool f0 = selfmode ? (mk0.x == 1) : (mk0.x != 0);
            bool f1 = selfmode ? (mk0.y == 1) : (mk0.y != 0);
            bool f2 = selfmode ? (mk1.x == 1) : (mk1.x != 0);
            bool f3 = selfmode ? (mk1.y == 1) : (mk1.y != 0);
            sc[n][0] = f0 ? bigneg : sc[n][0] * scale;
            sc[n][1] = f1 ? bigneg : sc[n][1] * scale;
            sc[n][2] = f2 ? bigneg : sc[n][2] * scale;
            sc[n][3] = f3 ? bigneg : sc[n][3] * scale;
        }

        // ---- online softmax ----
        float tm0 = -INFINITY, tm1 = -INFINITY;
        #pragma unroll
        for (int n = 0; n < 8; n++) {
            tm0 = fmaxf(tm0, fmaxf(sc[n][0], sc[n][1]));
            tm1 = fmaxf(tm1, fmaxf(sc[n][2], sc[n][3]));
        }
        tm0 = fmaxf(tm0, __shfl_xor_sync(0xffffffffu, tm0, 1));
        tm0 = fmaxf(tm0, __shfl_xor_sync(0xffffffffu, tm0, 2));
        tm1 = fmaxf(tm1, __shfl_xor_sync(0xffffffffu, tm1, 1));
        tm1 = fmaxf(tm1, __shfl_xor_sync(0xffffffffu, tm1, 2));
        float nm0 = fmaxf(m0, tm0), nm1 = fmaxf(m1, tm1);
        float c0 = __expf(m0 - nm0), c1 = __expf(m1 - nm1);
        m0 = nm0; m1 = nm1;

        float rs0 = 0.f, rs1 = 0.f;
        uint32_t pah[8][2], pal[8][2];
        #pragma unroll
        for (int n = 0; n < 8; n++) {
            float p0 = __expf(sc[n][0] - m0);
            float p1 = __expf(sc[n][1] - m0);
            float p2 = __expf(sc[n][2] - m1);
            float p3 = __expf(sc[n][3] - m1);
            rs0 += p0 + p1; rs1 += p2 + p3;
            __nv_bfloat162 h01 = __float22bfloat162_rn(make_float2(p0, p1));
            __nv_bfloat162 h23 = __float22bfloat162_rn(make_float2(p2, p3));
            pah[n][0] = bf2u(h01); pah[n][1] = bf2u(h23);
            __nv_bfloat162 q01 = __float22bfloat162_rn(make_float2(
                p0 - __bfloat162float(h01.x), p1 - __bfloat162float(h01.y)));
            __nv_bfloat162 q23 = __float22bfloat162_rn(make_float2(
                p2 - __bfloat162float(h23.x), p3 - __bfloat162float(h23.y)));
            pal[n][0] = bf2u(q01); pal[n][1] = bf2u(q23);
        }
        rs0 += __shfl_xor_sync(0xffffffffu, rs0, 1);
        rs0 += __shfl_xor_sync(0xffffffffu, rs0, 2);
        rs1 += __shfl_xor_sync(0xffffffffu, rs1, 1);
        rs1 += __shfl_xor_sync(0xffffffffu, rs1, 2);
        l0 = l0 * c0 + rs0;
        l1 = l1 * c1 + rs1;
        #pragma unroll
        for (int n = 0; n < 8; n++) {
            o[n][0] *= c0; o[n][1] *= c0; o[n][2] *= c1; o[n][3] *= c1;
        }

        // ---- O += P V (3-term) ----
        #pragma unroll
        for (int kk = 0; kk < 4; kk++) {
            uint32_t ah0 = pah[2*kk][0], ah1 = pah[2*kk][1];
            uint32_t ah2 = pah[2*kk+1][0], ah3 = pah[2*kk+1][1];
            uint32_t al0 = pal[2*kk][0], al1 = pal[2*kk][1];
            uint32_t al2 = pal[2*kk+1][0], al3 = pal[2*kk+1][1];
            uint32_t vrow = (uint32_t)(kk * 16 + (lane & 15));
            #pragma unroll
            for (int nbp = 0; nbp < 4; nbp++) {
                uint32_t vg = (uint32_t)(nbp * 2 + (lane >> 4));
                uint32_t vh0, vh1, vh2, vh3, vl0, vl1, vl2, vl3;
                LDSM_X4_T(vh0, vh1, vh2, vh3, su + ATT_VHI + offKV(vrow, vg));
                LDSM_X4_T(vl0, vl1, vl2, vl3, su + ATT_VLO + offKV(vrow, vg));
                MMA_BF16(o[2*nbp][0], o[2*nbp][1], o[2*nbp][2], o[2*nbp][3],
                         ah0, ah1, ah2, ah3, vh0, vh1);
                MMA_BF16(o[2*nbp+1][0], o[2*nbp+1][1], o[2*nbp+1][2], o[2*nbp+1][3],
                         ah0, ah1, ah2, ah3, vh2, vh3);
                MMA_BF16(o[2*nbp][0], o[2*nbp][1], o[2*nbp][2], o[2*nbp][3],
                         al0, al1, al2, al3, vh0, vh1);
                MMA_BF16(o[2*nbp+1][0], o[2*nbp+1][1], o[2*nbp+1][2], o[2*nbp+1][3],
                         al0, al1, al2, al3, vh2, vh3);
                MMA_BF16(o[2*nbp][0], o[2*nbp][1], o[2*nbp][2], o[2*nbp][3],
                         ah0, ah1, ah2, ah3, vl0, vl1);
                MMA_BF16(o[2*nbp+1][0], o[2*nbp+1][1], o[2*nbp+1][2], o[2*nbp+1][3],
                         ah0, ah1, ah2, ah3, vl2, vl3);
            }
        }
        __syncthreads();
    }

    // ---- epilogue: normalize, split to bf16 hi/lo ----
    const float i0 = 1.f / l0, i1 = 1.f / l1;
    const size_t gr0 = (size_t)b * S_ + q0 + wid * 16 + (lane >> 2);
    #pragma unroll
    for (int n = 0; n < 8; n++) {
        const int col = h * 64 + n * 8 + 2 * (lane & 3);
        float v0 = o[n][0] * i0, v1 = o[n][1] * i0;
        float v2 = o[n][2] * i1, v3 = o[n][3] * i1;
        __nv_bfloat162 h01 = __float22bfloat162_rn(make_float2(v0, v1));
        __nv_bfloat162 h23 = __float22bfloat162_rn(make_float2(v2, v3));
        __nv_bfloat162 l01 = __float22bfloat162_rn(make_float2(
            v0 - __bfloat162float(h01.x), v1 - __bfloat162float(h01.y)));
        __nv_bfloat162 l23 = __float22bfloat162_rn(make_float2(
            v2 - __bfloat162float(h23.x), v3 - __bfloat162float(h23.y)));
        *(__nv_bfloat162*)&Ohi[gr0 * D_ + col]       = h01;
        *(__nv_bfloat162*)&Ohi[(gr0 + 8) * D_ + col] = h23;
        *(__nv_bfloat162*)&Olo[gr0 * D_ + col]       = l01;
        *(__nv_bfloat162*)&Olo[(gr0 + 8) * D_ + col] = l23;
    }
}

// ============================================================
// prep: weight transpose + bf16 hi/lo split  W[K,N] -> Wt_hi/lo[N,K]
// ============================================================
__global__ __launch_bounds__(256)
void wsplit_kernel(const float* __restrict__ W, __nv_bfloat16* __restrict__ hi,
                   __nv_bfloat16* __restrict__ lo, int K, int N)
{
    __shared__ float t[32][33];
    const int tx = threadIdx.x, ty = threadIdx.y;      // 32 x 8
    const int n0 = blockIdx.x * 32, k0 = blockIdx.y * 32;
    #pragma unroll
    for (int r = 0; r < 4; r++)
        t[ty + r * 8][tx] = W[(size_t)(k0 + ty + r * 8) * N + n0 + tx];
    __syncthreads();
    #pragma unroll
    for (int r = 0; r < 4; r++) {
        float v = t[tx][ty + r * 8];
        size_t o = (size_t)(n0 + ty + r * 8) * K + k0 + tx;
        __nv_bfloat16 h = __float2bfloat16(v);
        hi[o] = h;
        lo[o] = __float2bfloat16(v - __bfloat162float(h));
    }
}

// prep: activation bf16 hi/lo split (elementwise)
__global__ __launch_bounds__(256)
void asplit_kernel(const float* __restrict__ A, __nv_bfloat16* __restrict__ hi,
                   __nv_bfloat16* __restrict__ lo, int n4)
{
    int i = blockIdx.x * 256 + threadIdx.x;
    if (i >= n4) return;
    float4 v = ((const float4*)A)[i];
    __nv_bfloat16 h0 = __float2bfloat16(v.x), h1 = __float2bfloat16(v.y);
    __nv_bfloat16 h2 = __float2bfloat16(v.z), h3 = __float2bfloat16(v.w);
    __nv_bfloat162* hp = (__nv_bfloat162*)hi;
    __nv_bfloat162* lp = (__nv_bfloat162*)lo;
    hp[2 * i + 0] = __nv_bfloat162(h0, h1);
    hp[2 * i + 1] = __nv_bfloat162(h2, h3);
    lp[2 * i + 0] = __nv_bfloat162(__float2bfloat16(v.x - __bfloat162float(h0)),
                                   __float2bfloat16(v.y - __bfloat162float(h1)));
    lp[2 * i + 1] = __nv_bfloat162(__float2bfloat16(v.z - __bfloat162float(h2)),
                                   __float2bfloat16(v.w - __bfloat162float(h3)));
}

// ============================================================
// LayerNorm. outmode 0: fp32 Y; outmode 1: bf16 hi/lo split
// ============================================================
__global__ __launch_bounds__(256)
void layernorm_kernel(const float* __restrict__ X, const float* __restrict__ gm,
                      const float* __restrict__ bt, float* __restrict__ Yf,
                      __nv_bfloat16* __restrict__ Yhi, __nv_bfloat16* __restrict__ Ylo,
                      int outmode)
{
    const int row = blockIdx.x;
    const int t = threadIdx.x;
    const float* x = X + (size_t)row * D_;

    float4 xv = *(const float4*)&x[t * 4];
    float s  = xv.x + xv.y + xv.z + xv.w;
    float ss = xv.x * xv.x + xv.y * xv.y + xv.z * xv.z + xv.w * xv.w;

    #pragma unroll
    for (int off = 16; off > 0; off >>= 1) {
        s  += __shfl_xor_sync(0xffffffffu, s, off);
        ss += __shfl_xor_sync(0xffffffffu, ss, off);
    }
    __shared__ float sbuf[8], ssbuf[8];
    if ((t & 31) == 0) { sbuf[t >> 5] = s; ssbuf[t >> 5] = ss; }
    __syncthreads();
    float ts = 0.f, tss = 0.f;
    #pragma unroll
    for (int i = 0; i < 8; i++) { ts += sbuf[i]; tss += ssbuf[i]; }

    const float invD = 1.f / (float)D_;
    float mu  = ts * invD;
    float var = tss * invD - mu * mu;
    float inv = rsqrtf(var + LN_EPS);

    float4 gv = *(const float4*)&gm[t * 4];
    float4 bv = *(const float4*)&bt[t * 4];
    float o0 = (xv.x - mu) * inv * gv.x + bv.x;
    float o1 = (xv.y - mu) * inv * gv.y + bv.y;
    float o2 = (xv.z - mu) * inv * gv.z + bv.z;
    float o3 = (xv.w - mu) * inv * gv.w + bv.w;

    if (outmode == 0) {
        float4 out = make_float4(o0, o1, o2, o3);
        *(float4*)&Yf[(size_t)row * D_ + t * 4] = out;
    } else {
        __nv_bfloat162 h01 = __float22bfloat162_rn(make_float2(o0, o1));
        __nv_bfloat162 h23 = __float22bfloat162_rn(make_float2(o2, o3));
        __nv_bfloat162 l01 = __float22bfloat162_rn(make_float2(
            o0 - __bfloat162float(h01.x), o1 - __bfloat162float(h01.y)));
        __nv_bfloat162 l23 = __float22bfloat162_rn(make_float2(
            o2 - __bfloat162float(h23.x), o3 - __bfloat162float(h23.y)));
        *(__nv_bfloat162*)&Yhi[(size_t)row * D_ + t * 4]     = h01;
        *(__nv_bfloat162*)&Yhi[(size_t)row * D_ + t * 4 + 2] = h23;
        *(__nv_bfloat162*)&Ylo[(size_t)row * D_ + t * 4]     = l01;
        *(__nv_bfloat162*)&Ylo[(size_t)row * D_ + t * 4 + 2] = l23;
    }
}

// ============================================================
// launch plumbing
// ============================================================
constexpr size_t MB1 = 1024ull * 1024ull;
constexpr size_t OFF_QW = 0,       OFF_KW = 1*MB1,  OFF_VW = 2*MB1,  OFF_OW = 3*MB1;
constexpr size_t OFF_F1W1 = 4*MB1, OFF_F1W2 = 8*MB1;
constexpr size_t OFF_CQW = 12*MB1, OFF_CKW = 13*MB1, OFF_CVW = 14*MB1, OFF_COW = 15*MB1;
constexpr size_t OFF_F2W1 = 16*MB1, OFF_F2W2 = 20*MB1;

struct Ctx {
    __nv_bfloat16 *wt_hi, *wt_lo;
    __nv_bfloat16 *a_hi, *a_lo, *b_hi, *b_lo;
    __nv_bfloat16 *qhi, *qlo, *khi, *klo, *vhi, *vlo;
    float *h2;
};

static inline void run_wsplit(const float* W, __nv_bfloat16* hi, __nv_bfloat16* lo,
                              int K, int N) {
    dim3 grid(N / 32, K / 32), block(32, 8);
    wsplit_kernel<<<grid, block>>>(W, hi, lo, K, N);
}
static inline void run_gemm(const __nv_bfloat16* Ahi, const __nv_bfloat16* Alo,
                            const Ctx& c, size_t woff, const float* bias,
                            float* Cf, __nv_bfloat16* Chi, __nv_bfloat16* Clo,
                            int M, int N, int K, int relu, int outmode) {
    dim3 grid(N / 128, M / 128), block(256);
    mma_gemm_kernel<<<grid, block, GEMM_SMEM>>>(
        Ahi, Alo, c.wt_hi + woff, c.wt_lo + woff, bias, Cf, Chi, Clo,
        M, N, K, relu, outmode);
}
static inline void run_attn(const Ctx& c, const int* mask,
                            __nv_bfloat16* ohi, __nv_bfloat16* olo, int selfmode) {
    dim3 grid(B_ * H_, S_ / 64), block(128);
    mma_attn_kernel<<<grid, block, ATT_SMEM>>>(
        c.qhi, c.qlo, c.khi, c.klo, c.vhi, c.vlo, mask, ohi, olo, selfmode);
}

extern "C" void kernel_launch(void* const* d_in, const int* in_sizes, int n_in,
                              void* d_out, int out_size)
{
    (void)in_sizes; (void)n_in; (void)out_size;
    const float* x    = (const float*)d_in[0];
    const float* y    = (const float*)d_in[1];
    const int*   mask = (const int*)  d_in[2];
    const float* qw   = (const float*)d_in[3];
    const float* qb   = (const float*)d_in[4];
    const float* kw   = (const float*)d_in[5];
    const float* kb   = (const float*)d_in[6];
    const float* vw   = (const float*)d_in[7];
    const float* vb   = (const float*)d_in[8];
    const float* ow   = (const float*)d_in[9];
    const float* ob   = (const float*)d_in[10];
    const float* f1w1 = (const float*)d_in[11];
    const float* f1b1 = (const float*)d_in[12];
    const float* f1w2 = (const float*)d_in[13];
    const float* f1b2 = (const float*)d_in[14];
    const float* ln1g = (const float*)d_in[15];
    const float* ln1b = (const float*)d_in[16];
    const float* cqw  = (const float*)d_in[17];
    const float* ckw  = (const float*)d_in[18];
    const float* cvw  = (const float*)d_in[19];
    const float* cow  = (const float*)d_in[20];
    const float* cob  = (const float*)d_in[21];
    const float* f2w1 = (const float*)d_in[22];
    const float* f2b1 = (const float*)d_in[23];
    const float* f2w2 = (const float*)d_in[24];
    const float* f2b2 = (const float*)d_in[25];
    const float* ln2g = (const float*)d_in[26];
    const float* ln2b = (const float*)d_in[27];
    float* out = (float*)d_out;

    Ctx c;
    cudaGetSymbolAddress((void**)&c.wt_hi, g_wt_hi);
    cudaGetSymbolAddress((void**)&c.wt_lo, g_wt_lo);
    cudaGetSymbolAddress((void**)&c.a_hi,  g_a_hi);
    cudaGetSymbolAddress((void**)&c.a_lo,  g_a_lo);
    cudaGetSymbolAddress((void**)&c.b_hi,  g_b_hi);
    cudaGetSymbolAddress((void**)&c.b_lo,  g_b_lo);
    cudaGetSymbolAddress((void**)&c.qhi,   g_qhi);
    cudaGetSymbolAddress((void**)&c.qlo,   g_qlo);
    cudaGetSymbolAddress((void**)&c.khi,   g_khi);
    cudaGetSymbolAddress((void**)&c.klo,   g_klo);
    cudaGetSymbolAddress((void**)&c.vhi,   g_vhi);
    cudaGetSymbolAddress((void**)&c.vlo,   g_vlo);
    cudaGetSymbolAddress((void**)&c.h2,    g_h2);

    cudaFuncSetAttribute(mma_gemm_kernel,
                         cudaFuncAttributeMaxDynamicSharedMemorySize, GEMM_SMEM);
    cudaFuncSetAttribute(mma_attn_kernel,
                         cudaFuncAttributeMaxDynamicSharedMemorySize, ATT_SMEM);

    // ---- weight prep (transpose + split) ----
    run_wsplit(qw,   c.wt_hi + OFF_QW,   c.wt_lo + OFF_QW,   D_, D_);
    run_wsplit(kw,   c.wt_hi + OFF_KW,   c.wt_lo + OFF_KW,   D_, D_);
    run_wsplit(vw,   c.wt_hi + OFF_VW,   c.wt_lo + OFF_VW,   D_, D_);
    run_wsplit(ow,   c.wt_hi + OFF_OW,   c.wt_lo + OFF_OW,   D_, D_);
    run_wsplit(f1w1, c.wt_hi + OFF_F1W1, c.wt_lo + OFF_F1W1, D_, 4 * D_);
    run_wsplit(f1w2, c.wt_hi + OFF_F1W2, c.wt_lo + OFF_F1W2, 4 * D_, D_);
    run_wsplit(cqw,  c.wt_hi + OFF_CQW,  c.wt_lo + OFF_CQW,  D_, D_);
    run_wsplit(ckw,  c.wt_hi + OFF_CKW,  c.wt_lo + OFF_CKW,  D_, D_);
    run_wsplit(cvw,  c.wt_hi + OFF_CVW,  c.wt_lo + OFF_CVW,  D_, D_);
    run_wsplit(cow,  c.wt_hi + OFF_COW,  c.wt_lo + OFF_COW,  D_, D_);
    run_wsplit(f2w1, c.wt_hi + OFF_F2W1, c.wt_lo + OFF_F2W1, D_, 4 * D_);
    run_wsplit(f2w2, c.wt_hi + OFF_F2W2, c.wt_lo + OFF_F2W2, 4 * D_, D_);

    const int n4 = M_ * D_ / 4;

    // ---- self-attention ----
    asplit_kernel<<<(n4 + 255) / 256, 256>>>(x, c.a_hi, c.a_lo, n4);
    run_gemm(c.a_hi, c.a_lo, c, OFF_QW, qb, nullptr, c.qhi, c.qlo, M_, D_, D_, 0, 1);
    run_gemm(c.a_hi, c.a_lo, c, OFF_KW, kb, nullptr, c.khi, c.klo, M_, D_, D_, 0, 1);
    run_gemm(c.a_hi, c.a_lo, c, OFF_VW, vb, nullptr, c.vhi, c.vlo, M_, D_, D_, 0, 1);
    run_attn(c, mask, c.b_hi, c.b_lo, 1);
    run_gemm(c.b_hi, c.b_lo, c, OFF_OW, ob, nullptr, c.a_hi, c.a_lo, M_, D_, D_, 0, 1);

    // ---- feedforward1 + norm1 ----
    run_gemm(c.a_hi, c.a_lo, c, OFF_F1W1, f1b1, nullptr, c.b_hi, c.b_lo, M_, 4*D_, D_, 1, 1);
    run_gemm(c.b_hi, c.b_lo, c, OFF_F1W2, f1b2, c.h2, nullptr, nullptr, M_, D_, 4*D_, 0, 0);
    layernorm_kernel<<<M_, 256>>>(c.h2, ln1g, ln1b, nullptr, c.a_hi, c.a_lo, 1);

    // ---- cross-attention: q from LN1 output, k/v from y ----
    run_gemm(c.a_hi, c.a_lo, c, OFF_CQW, nullptr, nullptr, c.qhi, c.qlo, M_, D_, D_, 0, 1);
    asplit_kernel<<<(n4 + 255) / 256, 256>>>(y, c.a_hi, c.a_lo, n4);
    run_gemm(c.a_hi, c.a_lo, c, OFF_CKW, nullptr, nullptr, c.khi, c.klo, M_, D_, D_, 0, 1);
    run_gemm(c.a_hi, c.a_lo, c, OFF_CVW, nullptr, nullptr, c.vhi, c.vlo, M_, D_, D_, 0, 1);
    run_attn(c, mask, c.b_hi, c.b_lo, 0);
    run_gemm(c.b_hi, c.b_lo, c, OFF_COW, cob, nullptr, c.a_hi, c.a_lo, M_, D_, D_, 0, 1);

    // ---- feedforward2 + norm2 ----
    run_gemm(c.a_hi, c.a_lo, c, OFF_F2W1, f2b1, nullptr, c.b_hi, c.b_lo, M_, 4*D_, D_, 1, 1);
    run_gemm(c.b_hi, c.b_lo, c, OFF_F2W2, f2b2, c.h2, nullptr, nullptr, M_, D_, 4*D_, 0, 0);
    layernorm_kernel<<<M_, 256>>>(c.h2, ln2g, ln2b, out, nullptr, nullptr, 0);
}

// round 5
// speedup vs baseline: 3.8827x; 1.0546x over previous
#include <cuda_runtime.h>
#include <cuda_bf16.h>
#include <math.h>
#include <stdint.h>

// ---------------- problem constants ----------------
constexpr int B_ = 2;
constexpr int S_ = 2048;
constexpr int D_ = 1024;
constexpr int H_ = 16;
constexpr int HD_ = 64;
constexpr int M_ = B_ * S_;          // 4096 rows
constexpr float LN_EPS = 1e-5f;
constexpr int BM_WORDS = M_ * S_ / 32;   // 262144 bitmap words

// ---------------- device scratch (no allocations allowed) ----------------
__device__ float g_h2 [M_ * D_];     // fp32 pre-LN buffer

constexpr size_t WT_ELEMS = 24ull * 1024 * 1024;    // all 12 transposed weights
__device__ __nv_bfloat16 g_wt_hi[WT_ELEMS];
__device__ __nv_bfloat16 g_wt_lo[WT_ELEMS];
__device__ __nv_bfloat16 g_a_hi[M_ * 4 * D_];
__device__ __nv_bfloat16 g_a_lo[M_ * 4 * D_];
__device__ __nv_bfloat16 g_b_hi[M_ * 4 * D_];
__device__ __nv_bfloat16 g_b_lo[M_ * 4 * D_];
__device__ __nv_bfloat16 g_qhi[M_ * D_], g_qlo[M_ * D_];
__device__ __nv_bfloat16 g_khi[M_ * D_], g_klo[M_ * D_];
__device__ __nv_bfloat16 g_vhi[M_ * D_], g_vlo[M_ * D_];
__device__ uint32_t g_bms[BM_WORDS];     // self-mask bitmap (mv==1)
__device__ uint32_t g_bmc[BM_WORDS];     // cross-mask bitmap (mv!=0)

// ---------------- PTX helpers (sm_80-class only) ----------------
__device__ __forceinline__ uint32_t smem_to_u32(const void* smem_ptr) {
    uint32_t addr;
    asm("{ .reg .u64 tmp; cvta.to.shared.u64 tmp, %1; cvt.u32.u64 %0, tmp; }"
        : "=r"(addr) : "l"(smem_ptr));
    return addr;
}
#define CP_ASYNC16(dst_u32, src_ptr) \
    asm volatile("cp.async.cg.shared.global [%0], [%1], 16;" \
        :: "r"(dst_u32), "l"(src_ptr))
#define CP_COMMIT() asm volatile("cp.async.commit_group;" ::: "memory")
#define CP_WAIT0()  asm volatile("cp.async.wait_group 0;" ::: "memory")
#define CP_WAIT1()  asm volatile("cp.async.wait_group 1;" ::: "memory")
#define CP_WAIT2()  asm volatile("cp.async.wait_group 2;" ::: "memory")
#define CP_WAIT3()  asm volatile("cp.async.wait_group 3;" ::: "memory")

#define LDSM_X4(r0, r1, r2, r3, addr) \
    asm volatile("ldmatrix.sync.aligned.m8n8.x4.shared.b16 {%0,%1,%2,%3}, [%4];" \
        : "=r"(r0), "=r"(r1), "=r"(r2), "=r"(r3) : "r"(addr))
#define LDSM_X4_T(r0, r1, r2, r3, addr) \
    asm volatile("ldmatrix.sync.aligned.m8n8.x4.trans.shared.b16 {%0,%1,%2,%3}, [%4];" \
        : "=r"(r0), "=r"(r1), "=r"(r2), "=r"(r3) : "r"(addr))

#define MMA_BF16(c0, c1, c2, c3, a0, a1, a2, a3, b0, b1) \
    asm volatile("mma.sync.aligned.m16n8k16.row.col.f32.bf16.bf16.f32 " \
        "{%0,%1,%2,%3}, {%4,%5,%6,%7}, {%8,%9}, {%0,%1,%2,%3};" \
        : "+f"(c0), "+f"(c1), "+f"(c2), "+f"(c3) \
        : "r"(a0), "r"(a1), "r"(a2), "r"(a3), "r"(b0), "r"(b1))

__device__ __forceinline__ uint32_t bf2u(__nv_bfloat162 v) {
    return *reinterpret_cast<uint32_t*>(&v);
}

// ============================================================
// HMMA split-bf16 GEMM (4-stage cp.async pipeline)
// ============================================================
constexpr int TILEB   = 8192;                // one 128x32 bf16 tile
constexpr int STAGEB  = 4 * TILEB;           // Ahi,Alo,Whi,Wlo = 32KB
constexpr int NSTAGE  = 4;
constexpr int GEMM_SMEM = NSTAGE * STAGEB;   // 131072

__device__ __forceinline__ uint32_t swz(uint32_t row, uint32_t gk) {
    return row * 64u + ((gk ^ ((row >> 1) & 3u)) << 4);
}

__global__ __launch_bounds__(256, 1)
void mma_gemm_kernel(const __nv_bfloat16* __restrict__ Ahi, const __nv_bfloat16* __restrict__ Alo,
                     const __nv_bfloat16* __restrict__ Whi, const __nv_bfloat16* __restrict__ Wlo,
                     const float* __restrict__ bias, float* __restrict__ Cf,
                     __nv_bfloat16* __restrict__ Chi, __nv_bfloat16* __restrict__ Clo,
                     int M, int N, int K, int relu, int outmode)
{
    extern __shared__ char smem[];
    const uint32_t su = smem_to_u32(smem);
    const int tid  = threadIdx.x;
    const int wid  = tid >> 5;
    const int lane = tid & 31;
    const int block_row = blockIdx.y * 128;
    const int block_col = blockIdx.x * 128;

    const __nv_bfloat16* basep[4] = { Ahi, Alo, Whi, Wlo };
    const int rowoff[4] = { block_row, block_row, block_col, block_col };

    auto load_stage = [&](int p, int kt) {
        const int k0 = kt * 32;
        #pragma unroll
        for (int i = 0; i < 8; i++) {
            int lin  = tid + (i << 8);
            int tile = lin >> 9;
            int rem  = lin & 511;
            int row  = rem >> 2;
            int g    = rem & 3;
            const __nv_bfloat16* src =
                basep[tile] + (size_t)(rowoff[tile] + row) * K + k0 + g * 8;
            uint32_t dst = su + p * STAGEB + tile * TILEB + swz(row, g);
            CP_ASYNC16(dst, src);
        }
    };

    float c[2][8][4];
    #pragma unroll
    for (int s = 0; s < 2; s++)
        #pragma unroll
        for (int n = 0; n < 8; n++)
            #pragma unroll
            for (int i = 0; i < 4; i++) c[s][n][i] = 0.f;

    const int wm = (wid & 3) * 32;
    const int wn = (wid >> 2) * 64;

    const int a_row  = (lane & 15);
    const int a_gsel = (lane >> 4);
    const int b_noff = ((lane >> 4) << 3) + (lane & 7);
    const int b_gsel = (lane >> 3) & 1;

    const int KT = K >> 5;
    load_stage(0, 0); CP_COMMIT();
    load_stage(1, 1); CP_COMMIT();
    load_stage(2, 2); CP_COMMIT();

    for (int kt = 0; kt < KT; kt++) {
        if (kt + 3 < KT) { load_stage((kt + 3) & 3, kt + 3); CP_COMMIT(); }
        const int ahead = KT - 1 - kt;
        if (ahead >= 3)      CP_WAIT3();
        else if (ahead == 2) CP_WAIT2();
        else if (ahead == 1) CP_WAIT1();
        else                 CP_WAIT0();
        __syncthreads();

        const uint32_t stAhi = su + (kt & 3) * STAGEB;
        const uint32_t stAlo = stAhi + TILEB;
        const uint32_t stWhi = stAhi + 2 * TILEB;
        const uint32_t stWlo = stAhi + 3 * TILEB;

        #pragma unroll
        for (int kk = 0; kk < 2; kk++) {
            uint32_t ah[2][4], al[2][4], bh[8][2], bl[8][2];
            #pragma unroll
            for (int s = 0; s < 2; s++) {
                uint32_t ro = (uint32_t)(wm + s * 16 + a_row);
                uint32_t gk = (uint32_t)(kk * 2 + a_gsel);
                LDSM_X4(ah[s][0], ah[s][1], ah[s][2], ah[s][3], stAhi + swz(ro, gk));
                LDSM_X4(al[s][0], al[s][1], al[s][2], al[s][3], stAlo + swz(ro, gk));
            }
            #pragma unroll
            for (int grp = 0; grp < 4; grp++) {
                uint32_t ro = (uint32_t)(wn + grp * 16 + b_noff);
                uint32_t gk = (uint32_t)(kk * 2 + b_gsel);
                LDSM_X4(bh[2*grp][0], bh[2*grp][1], bh[2*grp+1][0], bh[2*grp+1][1],
                        stWhi + swz(ro, gk));
                LDSM_X4(bl[2*grp][0], bl[2*grp][1], bl[2*grp+1][0], bl[2*grp+1][1],
                        stWlo + swz(ro, gk));
            }
            #pragma unroll
            for (int s = 0; s < 2; s++)
                #pragma unroll
                for (int n = 0; n < 8; n++)
                    MMA_BF16(c[s][n][0], c[s][n][1], c[s][n][2], c[s][n][3],
                             ah[s][0], ah[s][1], ah[s][2], ah[s][3],
                             bh[n][0], bh[n][1]);
            #pragma unroll
            for (int s = 0; s < 2; s++)
                #pragma unroll
                for (int n = 0; n < 8; n++)
                    MMA_BF16(c[s][n][0], c[s][n][1], c[s][n][2], c[s][n][3],
                             ah[s][0], ah[s][1], ah[s][2], ah[s][3],
                             bl[n][0], bl[n][1]);
            #pragma unroll
            for (int s = 0; s < 2; s++)
                #pragma unroll
                for (int n = 0; n < 8; n++)
                    MMA_BF16(c[s][n][0], c[s][n][1], c[s][n][2], c[s][n][3],
                             al[s][0], al[s][1], al[s][2], al[s][3],
                             bh[n][0], bh[n][1]);
        }
        __syncthreads();
    }

    const int gp  = lane >> 2;
    const int tig = lane & 3;
    #pragma unroll
    for (int s = 0; s < 2; s++) {
        const int r0 = block_row + wm + s * 16 + gp;
        #pragma unroll
        for (int n = 0; n < 8; n++) {
            const int col = block_col + wn + n * 8 + tig * 2;
            float b0 = bias ? __ldg(&bias[col])     : 0.f;
            float b1 = bias ? __ldg(&bias[col + 1]) : 0.f;
            float v0 = c[s][n][0] + b0, v1 = c[s][n][1] + b1;
            float v2 = c[s][n][2] + b0, v3 = c[s][n][3] + b1;
            if (relu) {
                v0 = fmaxf(v0, 0.f); v1 = fmaxf(v1, 0.f);
                v2 = fmaxf(v2, 0.f); v3 = fmaxf(v3, 0.f);
            }
            if (outmode == 0) {
                *(float2*)&Cf[(size_t)r0 * N + col]       = make_float2(v0, v1);
                *(float2*)&Cf[(size_t)(r0 + 8) * N + col] = make_float2(v2, v3);
            } else {
                __nv_bfloat162 h01 = __float22bfloat162_rn(make_float2(v0, v1));
                __nv_bfloat162 h23 = __float22bfloat162_rn(make_float2(v2, v3));
                __nv_bfloat162 l01 = __float22bfloat162_rn(make_float2(
                    v0 - __bfloat162float(h01.x), v1 - __bfloat162float(h01.y)));
                __nv_bfloat162 l23 = __float22bfloat162_rn(make_float2(
                    v2 - __bfloat162float(h23.x), v3 - __bfloat162float(h23.y)));
                *(__nv_bfloat162*)&Chi[(size_t)r0 * N + col]       = h01;
                *(__nv_bfloat162*)&Chi[(size_t)(r0 + 8) * N + col] = h23;
                *(__nv_bfloat162*)&Clo[(size_t)r0 * N + col]       = l01;
                *(__nv_bfloat162*)&Clo[(size_t)(r0 + 8) * N + col] = l23;
            }
        }
    }
}

// ============================================================
// MMA flash attention: double-buffered K/V, bitmap mask.
// CTA: 64 q-rows, 4 warps, Bc=64.
// ============================================================
constexpr int ATT_STAGE = 32768;             // Khi,Klo,Vhi,Vlo tiles (8KB each)
constexpr int ATT_SMEM  = 2 * ATT_STAGE;     // 65536

__device__ __forceinline__ uint32_t offKV(uint32_t row, uint32_t g) {
    return row * 128u + ((g ^ (row & 7u)) << 4);
}

__global__ __launch_bounds__(128)
void mma_attn_kernel(const __nv_bfloat16* __restrict__ Qhi, const __nv_bfloat16* __restrict__ Qlo,
                     const __nv_bfloat16* __restrict__ Khi, const __nv_bfloat16* __restrict__ Klo,
                     const __nv_bfloat16* __restrict__ Vhi, const __nv_bfloat16* __restrict__ Vlo,
                     const uint32_t* __restrict__ bm,
                     __nv_bfloat16* __restrict__ Ohi, __nv_bfloat16* __restrict__ Olo,
                     int selfmode)
{
    extern __shared__ char smem[];
    const uint32_t su = smem_to_u32(smem);
    const int tid = threadIdx.x, wid = tid >> 5, lane = tid & 31;
    const int b = blockIdx.x >> 4, h = blockIdx.x & 15;
    const int q0 = blockIdx.y * 64;

    // ---- stage Q tiles through smem (stage 0 slots), build A fragments ----
    #pragma unroll
    for (int i = 0; i < 8; i++) {
        int lin = tid + (i << 7);
        int t = lin >> 9, rem = lin & 511, row = rem >> 3, g = rem & 7;
        const __nv_bfloat16* src = (t ? Qlo : Qhi) +
            ((size_t)b * S_ + q0 + row) * D_ + h * 64 + g * 8;
        CP_ASYNC16(su + t * 8192 + offKV(row, g), src);
    }
    CP_COMMIT(); CP_WAIT0(); __syncthreads();

    uint32_t qa_hi[4][4], qa_lo[4][4];
    {
        const uint32_t arow = (uint32_t)(wid * 16 + (lane & 15));
        const uint32_t ag = (uint32_t)(lane >> 4);
        #pragma unroll
        for (int kk = 0; kk < 4; kk++) {
            LDSM_X4(qa_hi[kk][0], qa_hi[kk][1], qa_hi[kk][2], qa_hi[kk][3],
                    su + offKV(arow, kk * 2 + ag));
            LDSM_X4(qa_lo[kk][0], qa_lo[kk][1], qa_lo[kk][2], qa_lo[kk][3],
                    su + 8192 + offKV(arow, kk * 2 + ag));
        }
    }
    __syncthreads();

    float o[8][4];
    #pragma unroll
    for (int n = 0; n < 8; n++)
        #pragma unroll
        for (int i = 0; i < 4; i++) o[n][i] = 0.f;
    float m0 = -INFINITY, m1 = -INFINITY, l0 = 0.f, l1 = 0.f;
    const float scale = 0.125f;
    const float bigneg = selfmode ? -3.0e38f : -1.25e8f;

    const int b_noff = ((lane >> 4) << 3) + (lane & 7);
    const int b_gsel = (lane >> 3) & 1;
    const int mr0 = wid * 16 + (lane >> 2);
    const int msh = (2 * (lane & 3));   // bit shift base within 8-col group

    const __nv_bfloat16* kvp[4] = { Khi, Klo, Vhi, Vlo };
    const uint32_t* bmr0 = bm + ((size_t)b * S_ + q0 + mr0) * (S_ / 32);
    const uint32_t* bmr1 = bmr0 + 8 * (S_ / 32);

    auto load_kv = [&](int buf, int jt) {
        const int j0 = jt * 64;
        #pragma unroll
        for (int i = 0; i < 16; i++) {
            int lin = tid + (i << 7);
            int t = lin >> 9, rem = lin & 511, row = rem >> 3, g = rem & 7;
            CP_ASYNC16(su + buf * ATT_STAGE + t * 8192 + offKV(row, g),
                       kvp[t] + ((size_t)b * S_ + j0 + row) * D_ + h * 64 + g * 8);
        }
    };

    load_kv(0, 0); CP_COMMIT();

    for (int jt = 0; jt < 32; jt++) {
        if (jt + 1 < 32) { load_kv((jt + 1) & 1, jt + 1); CP_COMMIT(); CP_WAIT1(); }
        else             { CP_WAIT0(); }
        __syncthreads();

        const uint32_t sb = su + (jt & 1) * ATT_STAGE;

        // mask bitmap words for this 64-col tile
        const uint32_t u00 = __ldg(&bmr0[jt * 2]),     u01 = __ldg(&bmr0[jt * 2 + 1]);
        const uint32_t u10 = __ldg(&bmr1[jt * 2]),     u11 = __ldg(&bmr1[jt * 2 + 1]);

        // ---- S = Q K^T (3-term) ----
        float sc[8][4];
        #pragma unroll
        for (int n = 0; n < 8; n++)
            #pragma unroll
            for (int i = 0; i < 4; i++) sc[n][i] = 0.f;

        #pragma unroll
        for (int kk = 0; kk < 4; kk++) {
            uint32_t kbh[8][2], kbl[8][2];
            #pragma unroll
            for (int grp = 0; grp < 4; grp++) {
                uint32_t ro = (uint32_t)(grp * 16 + b_noff);
                uint32_t gd = (uint32_t)(kk * 2 + b_gsel);
                LDSM_X4(kbh[2*grp][0], kbh[2*grp][1], kbh[2*grp+1][0], kbh[2*grp+1][1],
                        sb + offKV(ro, gd));
                LDSM_X4(kbl[2*grp][0], kbl[2*grp][1], kbl[2*grp+1][0], kbl[2*grp+1][1],
                        sb + 8192 + offKV(ro, gd));
            }
            #pragma unroll
            for (int n = 0; n < 8; n++)
                MMA_BF16(sc[n][0], sc[n][1], sc[n][2], sc[n][3],
                         qa_hi[kk][0], qa_hi[kk][1], qa_hi[kk][2], qa_hi[kk][3],
                         kbh[n][0], kbh[n][1]);
            #pragma unroll
            for (int n = 0; n < 8; n++)
                MMA_BF16(sc[n][0], sc[n][1], sc[n][2], sc[n][3],
                         qa_hi[kk][0], qa_hi[kk][1], qa_hi[kk][2], qa_hi[kk][3],
                         kbl[n][0], kbl[n][1]);
            #pragma unroll
            for (int n = 0; n < 8; n++)
                MMA_BF16(sc[n][0], sc[n][1], sc[n][2], sc[n][3],
                         qa_lo[kk][0], qa_lo[kk][1], qa_lo[kk][2], qa_lo[kk][3],
                         kbh[n][0], kbh[n][1]);
        }

        // ---- mask + scale (bitmap) ----
        #pragma unroll
        for (int n = 0; n < 8; n++) {
            const uint32_t w0 = (n < 4) ? u00 : u01;
            const uint32_t w1 = (n < 4) ? u10 : u11;
            const int sh = ((n * 8) & 31) + msh;
            bool f0 = (w0 >> sh) & 1, f1 = (w0 >> (sh + 1)) & 1;
            bool f2 = (w1 >> sh) & 1, f3 = (w1 >> (sh + 1)) & 1;
            sc[n][0] = f0 ? bigneg : sc[n][0] * scale;
            sc[n][1] = f1 ? bigneg : sc[n][1] * scale;
            sc[n][2] = f2 ? bigneg : sc[n][2] * scale;
            sc[n][3] = f3 ? bigneg : sc[n][3] * scale;
        }

        // ---- online softmax ----
        float tm0 = -INFINITY, tm1 = -INFINITY;
        #pragma unroll
        for (int n = 0; n < 8; n++) {
            tm0 = fmaxf(tm0, fmaxf(sc[n][0], sc[n][1]));
            tm1 = fmaxf(tm1, fmaxf(sc[n][2], sc[n][3]));
        }
        tm0 = fmaxf(tm0, __shfl_xor_sync(0xffffffffu, tm0, 1));
        tm0 = fmaxf(tm0, __shfl_xor_sync(0xffffffffu, tm0, 2));
        tm1 = fmaxf(tm1, __shfl_xor_sync(0xffffffffu, tm1, 1));
        tm1 = fmaxf(tm1, __shfl_xor_sync(0xffffffffu, tm1, 2));
        float nm0 = fmaxf(m0, tm0), nm1 = fmaxf(m1, tm1);
        float c0 = __expf(m0 - nm0), c1 = __expf(m1 - nm1);
        m0 = nm0; m1 = nm1;

        float rs0 = 0.f, rs1 = 0.f;
        uint32_t pah[8][2], pal[8][2];
        #pragma unroll
        for (int n = 0; n < 8; n++) {
            float p0 = __expf(sc[n][0] - m0);
            float p1 = __expf(sc[n][1] - m0);
            float p2 = __expf(sc[n][2] - m1);
            float p3 = __expf(sc[n][3] - m1);
            rs0 += p0 + p1; rs1 += p2 + p3;
            __nv_bfloat162 h01 = __float22bfloat162_rn(make_float2(p0, p1));
            __nv_bfloat162 h23 = __float22bfloat162_rn(make_float2(p2, p3));
            pah[n][0] = bf2u(h01); pah[n][1] = bf2u(h23);
            __nv_bfloat162 q01 = __float22bfloat162_rn(make_float2(
                p0 - __bfloat162float(h01.x), p1 - __bfloat162float(h01.y)));
            __nv_bfloat162 q23 = __float22bfloat162_rn(make_float2(
                p2 - __bfloat162float(h23.x), p3 - __bfloat162float(h23.y)));
            pal[n][0] = bf2u(q01); pal[n][1] = bf2u(q23);
        }
        rs0 += __shfl_xor_sync(0xffffffffu, rs0, 1);
        rs0 += __shfl_xor_sync(0xffffffffu, rs0, 2);
        rs1 += __shfl_xor_sync(0xffffffffu, rs1, 1);
        rs1 += __shfl_xor_sync(0xffffffffu, rs1, 2);
        l0 = l0 * c0 + rs0;
        l1 = l1 * c1 + rs1;
        #pragma unroll
        for (int n = 0; n < 8; n++) {
            o[n][0] *= c0; o[n][1] *= c0; o[n][2] *= c1; o[n][3] *= c1;
        }

        // ---- O += P V (3-term) ----
        #pragma unroll
        for (int kk = 0; kk < 4; kk++) {
            uint32_t ah0 = pah[2*kk][0], ah1 = pah[2*kk][1];
            uint32_t ah2 = pah[2*kk+1][0], ah3 = pah[2*kk+1][1];
            uint32_t al0 = pal[2*kk][0], al1 = pal[2*kk][1];
            uint32_t al2 = pal[2*kk+1][0], al3 = pal[2*kk+1][1];
            uint32_t vrow = (uint32_t)(kk * 16 + (lane & 15));
            #pragma unroll
            for (int nbp = 0; nbp < 4; nbp++) {
                uint32_t vg = (uint32_t)(nbp * 2 + (lane >> 4));
                uint32_t vh0, vh1, vh2, vh3, vl0, vl1, vl2, vl3;
                LDSM_X4_T(vh0, vh1, vh2, vh3, sb + 16384 + offKV(vrow, vg));
                LDSM_X4_T(vl0, vl1, vl2, vl3, sb + 24576 + offKV(vrow, vg));
                MMA_BF16(o[2*nbp][0], o[2*nbp][1], o[2*nbp][2], o[2*nbp][3],
                         ah0, ah1, ah2, ah3, vh0, vh1);
                MMA_BF16(o[2*nbp+1][0], o[2*nbp+1][1], o[2*nbp+1][2], o[2*nbp+1][3],
                         ah0, ah1, ah2, ah3, vh2, vh3);
                MMA_BF16(o[2*nbp][0], o[2*nbp][1], o[2*nbp][2], o[2*nbp][3],
                         al0, al1, al2, al3, vh0, vh1);
                MMA_BF16(o[2*nbp+1][0], o[2*nbp+1][1], o[2*nbp+1][2], o[2*nbp+1][3],
                         al0, al1, al2, al3, vh2, vh3);
                MMA_BF16(o[2*nbp][0], o[2*nbp][1], o[2*nbp][2], o[2*nbp][3],
                         ah0, ah1, ah2, ah3, vl0, vl1);
                MMA_BF16(o[2*nbp+1][0], o[2*nbp+1][1], o[2*nbp+1][2], o[2*nbp+1][3],
                         ah0, ah1, ah2, ah3, vl2, vl3);
            }
        }
        __syncthreads();
    }

    // ---- epilogue: normalize, split to bf16 hi/lo ----
    const float i0 = 1.f / l0, i1 = 1.f / l1;
    const size_t gr0 = (size_t)b * S_ + q0 + wid * 16 + (lane >> 2);
    #pragma unroll
    for (int n = 0; n < 8; n++) {
        const int col = h * 64 + n * 8 + 2 * (lane & 3);
        float v0 = o[n][0] * i0, v1 = o[n][1] * i0;
        float v2 = o[n][2] * i1, v3 = o[n][3] * i1;
        __nv_bfloat162 h01 = __float22bfloat162_rn(make_float2(v0, v1));
        __nv_bfloat162 h23 = __float22bfloat162_rn(make_float2(v2, v3));
        __nv_bfloat162 l01 = __float22bfloat162_rn(make_float2(
            v0 - __bfloat162float(h01.x), v1 - __bfloat162float(h01.y)));
        __nv_bfloat162 l23 = __float22bfloat162_rn(make_float2(
            v2 - __bfloat162float(h23.x), v3 - __bfloat162float(h23.y)));
        *(__nv_bfloat162*)&Ohi[gr0 * D_ + col]       = h01;
        *(__nv_bfloat162*)&Ohi[(gr0 + 8) * D_ + col] = h23;
        *(__nv_bfloat162*)&Olo[gr0 * D_ + col]       = l01;
        *(__nv_bfloat162*)&Olo[(gr0 + 8) * D_ + col] = l23;
    }
}

// ============================================================
// prep: mask -> bitmaps (self: ==1, cross: !=0). One warp per 32 words.
// ============================================================
__global__ __launch_bounds__(256)
void mprep_kernel(const int* __restrict__ mask, uint32_t* __restrict__ bms,
                  uint32_t* __restrict__ bmc)
{
    const int lane = threadIdx.x & 31;
    const size_t w = ((size_t)blockIdx.x * blockDim.x + threadIdx.x) >> 5;
    const size_t base = w * 1024;
    #pragma unroll 4
    for (int i = 0; i < 32; i++) {
        int mv = mask[base + i * 32 + lane];
        uint32_t s = __ballot_sync(0xffffffffu, mv == 1);
        uint32_t c = __ballot_sync(0xffffffffu, mv != 0);
        if (lane == 0) { bms[w * 32 + i] = s; bmc[w * 32 + i] = c; }
    }
}

// ============================================================
// prep: weight transpose + bf16 hi/lo split
// ============================================================
__global__ __launch_bounds__(256)
void wsplit_kernel(const float* __restrict__ W, __nv_bfloat16* __restrict__ hi,
                   __nv_bfloat16* __restrict__ lo, int K, int N)
{
    __shared__ float t[32][33];
    const int tx = threadIdx.x, ty = threadIdx.y;
    const int n0 = blockIdx.x * 32, k0 = blockIdx.y * 32;
    #pragma unroll
    for (int r = 0; r < 4; r++)
        t[ty + r * 8][tx] = W[(size_t)(k0 + ty + r * 8) * N + n0 + tx];
    __syncthreads();
    #pragma unroll
    for (int r = 0; r < 4; r++) {
        float v = t[tx][ty + r * 8];
        size_t o = (size_t)(n0 + ty + r * 8) * K + k0 + tx;
        __nv_bfloat16 h = __float2bfloat16(v);
        hi[o] = h;
        lo[o] = __float2bfloat16(v - __bfloat162float(h));
    }
}

// batched version for the 8 DxD weights
struct WB8 {
    const float* src[8];
    __nv_bfloat16* hi[8];
    __nv_bfloat16* lo[8];
};
__global__ __launch_bounds__(256)
void wsplit8_kernel(WB8 p)
{
    __shared__ float t[32][33];
    const int tx = threadIdx.x, ty = threadIdx.y;
    const int n0 = blockIdx.x * 32, k0 = blockIdx.y * 32;
    const int wsel = blockIdx.z;
    const float* W = p.src[wsel];
    __nv_bfloat16* hi = p.hi[wsel];
    __nv_bfloat16* lo = p.lo[wsel];
    #pragma unroll
    for (int r = 0; r < 4; r++)
        t[ty + r * 8][tx] = W[(size_t)(k0 + ty + r * 8) * D_ + n0 + tx];
    __syncthreads();
    #pragma unroll
    for (int r = 0; r < 4; r++) {
        float v = t[tx][ty + r * 8];
        size_t o = (size_t)(n0 + ty + r * 8) * D_ + k0 + tx;
        __nv_bfloat16 h = __float2bfloat16(v);
        hi[o] = h;
        lo[o] = __float2bfloat16(v - __bfloat162float(h));
    }
}

// prep: activation bf16 hi/lo split
__global__ __launch_bounds__(256)
void asplit_kernel(const float* __restrict__ A, __nv_bfloat16* __restrict__ hi,
                   __nv_bfloat16* __restrict__ lo, int n4)
{
    int i = blockIdx.x * 256 + threadIdx.x;
    if (i >= n4) return;
    float4 v = ((const float4*)A)[i];
    __nv_bfloat16 h0 = __float2bfloat16(v.x), h1 = __float2bfloat16(v.y);
    __nv_bfloat16 h2 = __float2bfloat16(v.z), h3 = __float2bfloat16(v.w);
    __nv_bfloat162* hp = (__nv_bfloat162*)hi;
    __nv_bfloat162* lp = (__nv_bfloat162*)lo;
    hp[2 * i + 0] = __nv_bfloat162(h0, h1);
    hp[2 * i + 1] = __nv_bfloat162(h2, h3);
    lp[2 * i + 0] = __nv_bfloat162(__float2bfloat16(v.x - __bfloat162float(h0)),
                                   __float2bfloat16(v.y - __bfloat162float(h1)));
    lp[2 * i + 1] = __nv_bfloat162(__float2bfloat16(v.z - __bfloat162float(h2)),
                                   __float2bfloat16(v.w - __bfloat162float(h3)));
}

// ============================================================
// LayerNorm
// ============================================================
__global__ __launch_bounds__(256)
void layernorm_kernel(const float* __restrict__ X, const float* __restrict__ gm,
                      const float* __restrict__ bt, float* __restrict__ Yf,
                      __nv_bfloat16* __restrict__ Yhi, __nv_bfloat16* __restrict__ Ylo,
                      int outmode)
{
    const int row = blockIdx.x;
    const int t = threadIdx.x;
    const float* x = X + (size_t)row * D_;

    float4 xv = *(const float4*)&x[t * 4];
    float s  = xv.x + xv.y + xv.z + xv.w;
    float ss = xv.x * xv.x + xv.y * xv.y + xv.z * xv.z + xv.w * xv.w;

    #pragma unroll
    for (int off = 16; off > 0; off >>= 1) {
        s  += __shfl_xor_sync(0xffffffffu, s, off);
        ss += __shfl_xor_sync(0xffffffffu, ss, off);
    }
    __shared__ float sbuf[8], ssbuf[8];
    if ((t & 31) == 0) { sbuf[t >> 5] = s; ssbuf[t >> 5] = ss; }
    __syncthreads();
    float ts = 0.f, tss = 0.f;
    #pragma unroll
    for (int i = 0; i < 8; i++) { ts += sbuf[i]; tss += ssbuf[i]; }

    const float invD = 1.f / (float)D_;
    float mu  = ts * invD;
    float var = tss * invD - mu * mu;
    float inv = rsqrtf(var + LN_EPS);

    float4 gv = *(const float4*)&gm[t * 4];
    float4 bv = *(const float4*)&bt[t * 4];
    float o0 = (xv.x - mu) * inv * gv.x + bv.x;
    float o1 = (xv.y - mu) * inv * gv.y + bv.y;
    float o2 = (xv.z - mu) * inv * gv.z + bv.z;
    float o3 = (xv.w - mu) * inv * gv.w + bv.w;

    if (outmode == 0) {
        *(float4*)&Yf[(size_t)row * D_ + t * 4] = make_float4(o0, o1, o2, o3);
    } else {
        __nv_bfloat162 h01 = __float22bfloat162_rn(make_float2(o0, o1));
        __nv_bfloat162 h23 = __float22bfloat162_rn(make_float2(o2, o3));
        __nv_bfloat162 l01 = __float22bfloat162_rn(make_float2(
            o0 - __bfloat162float(h01.x), o1 - __bfloat162float(h01.y)));
        __nv_bfloat162 l23 = __float22bfloat162_rn(make_float2(
            o2 - __bfloat162float(h23.x), o3 - __bfloat162float(h23.y)));
        *(__nv_bfloat162*)&Yhi[(size_t)row * D_ + t * 4]     = h01;
        *(__nv_bfloat162*)&Yhi[(size_t)row * D_ + t * 4 + 2] = h23;
        *(__nv_bfloat162*)&Ylo[(size_t)row * D_ + t * 4]     = l01;
        *(__nv_bfloat162*)&Ylo[(size_t)row * D_ + t * 4 + 2] = l23;
    }
}

// ============================================================
// launch plumbing
// ============================================================
constexpr size_t MB1 = 1024ull * 1024ull;
constexpr size_t OFF_QW = 0,       OFF_KW = 1*MB1,  OFF_VW = 2*MB1,  OFF_OW = 3*MB1;
constexpr size_t OFF_F1W1 = 4*MB1, OFF_F1W2 = 8*MB1;
constexpr size_t OFF_CQW = 12*MB1, OFF_CKW = 13*MB1, OFF_CVW = 14*MB1, OFF_COW = 15*MB1;
constexpr size_t OFF_F2W1 = 16*MB1, OFF_F2W2 = 20*MB1;

struct Ctx {
    __nv_bfloat16 *wt_hi, *wt_lo;
    __nv_bfloat16 *a_hi, *a_lo, *b_hi, *b_lo;
    __nv_bfloat16 *qhi, *qlo, *khi, *klo, *vhi, *vlo;
    float *h2;
    uint32_t *bms, *bmc;
};

static inline void run_gemm(const __nv_bfloat16* Ahi, const __nv_bfloat16* Alo,
                            const Ctx& c, size_t woff, const float* bias,
                            float* Cf, __nv_bfloat16* Chi, __nv_bfloat16* Clo,
                            int M, int N, int K, int relu, int outmode) {
    dim3 grid(N / 128, M / 128), block(256);
    mma_gemm_kernel<<<grid, block, GEMM_SMEM>>>(
        Ahi, Alo, c.wt_hi + woff, c.wt_lo + woff, bias, Cf, Chi, Clo,
        M, N, K, relu, outmode);
}
static inline void run_attn(const Ctx& c, const uint32_t* bm,
                            __nv_bfloat16* ohi, __nv_bfloat16* olo, int selfmode) {
    dim3 grid(B_ * H_, S_ / 64), block(128);
    mma_attn_kernel<<<grid, block, ATT_SMEM>>>(
        c.qhi, c.qlo, c.khi, c.klo, c.vhi, c.vlo, bm, ohi, olo, selfmode);
}

extern "C" void kernel_launch(void* const* d_in, const int* in_sizes, int n_in,
                              void* d_out, int out_size)
{
    (void)in_sizes; (void)n_in; (void)out_size;
    const float* x    = (const float*)d_in[0];
    const float* y    = (const float*)d_in[1];
    const int*   mask = (const int*)  d_in[2];
    const float* qw   = (const float*)d_in[3];
    const float* qb   = (const float*)d_in[4];
    const float* kw   = (const float*)d_in[5];
    const float* kb   = (const float*)d_in[6];
    const float* vw   = (const float*)d_in[7];
    const float* vb   = (const float*)d_in[8];
    const float* ow   = (const float*)d_in[9];
    const float* ob   = (const float*)d_in[10];
    const float* f1w1 = (const float*)d_in[11];
    const float* f1b1 = (const float*)d_in[12];
    const float* f1w2 = (const float*)d_in[13];
    const float* f1b2 = (const float*)d_in[14];
    const float* ln1g = (const float*)d_in[15];
    const float* ln1b = (const float*)d_in[16];
    const float* cqw  = (const float*)d_in[17];
    const float* ckw  = (const float*)d_in[18];
    const float* cvw  = (const float*)d_in[19];
    const float* cow  = (const float*)d_in[20];
    const float* cob  = (const float*)d_in[21];
    const float* f2w1 = (const float*)d_in[22];
    const float* f2b1 = (const float*)d_in[23];
    const float* f2w2 = (const float*)d_in[24];
    const float* f2b2 = (const float*)d_in[25];
    const float* ln2g = (const float*)d_in[26];
    const float* ln2b = (const float*)d_in[27];
    float* out = (float*)d_out;

    Ctx c;
    cudaGetSymbolAddress((void**)&c.wt_hi, g_wt_hi);
    cudaGetSymbolAddress((void**)&c.wt_lo, g_wt_lo);
    cudaGetSymbolAddress((void**)&c.a_hi,  g_a_hi);
    cudaGetSymbolAddress((void**)&c.a_lo,  g_a_lo);
    cudaGetSymbolAddress((void**)&c.b_hi,  g_b_hi);
    cudaGetSymbolAddress((void**)&c.b_lo,  g_b_lo);
    cudaGetSymbolAddress((void**)&c.qhi,   g_qhi);
    cudaGetSymbolAddress((void**)&c.qlo,   g_qlo);
    cudaGetSymbolAddress((void**)&c.khi,   g_khi);
    cudaGetSymbolAddress((void**)&c.klo,   g_klo);
    cudaGetSymbolAddress((void**)&c.vhi,   g_vhi);
    cudaGetSymbolAddress((void**)&c.vlo,   g_vlo);
    cudaGetSymbolAddress((void**)&c.h2,    g_h2);
    cudaGetSymbolAddress((void**)&c.bms,   g_bms);
    cudaGetSymbolAddress((void**)&c.bmc,   g_bmc);

    cudaFuncSetAttribute(mma_gemm_kernel,
                         cudaFuncAttributeMaxDynamicSharedMemorySize, GEMM_SMEM);
    cudaFuncSetAttribute(mma_attn_kernel,
                         cudaFuncAttributeMaxDynamicSharedMemorySize, ATT_SMEM);

    // ---- prep: mask bitmaps ----
    mprep_kernel<<<BM_WORDS / 32 / 8, 256>>>(mask, c.bms, c.bmc);

    // ---- weight prep ----
    {
        WB8 p;
        const float* srcs[8] = { qw, kw, vw, ow, cqw, ckw, cvw, cow };
        const size_t offs[8] = { OFF_QW, OFF_KW, OFF_VW, OFF_OW,
                                 OFF_CQW, OFF_CKW, OFF_CVW, OFF_COW };
        for (int i = 0; i < 8; i++) {
            p.src[i] = srcs[i];
            p.hi[i]  = c.wt_hi + offs[i];
            p.lo[i]  = c.wt_lo + offs[i];
        }
        dim3 grid(32, 32, 8), block(32, 8);
        wsplit8_kernel<<<grid, block>>>(p);
    }
    {
        dim3 block(32, 8);
        dim3 g1(4 * D_ / 32, D_ / 32), g2(D_ / 32, 4 * D_ / 32);
        wsplit_kernel<<<g1, block>>>(f1w1, c.wt_hi + OFF_F1W1, c.wt_lo + OFF_F1W1, D_, 4 * D_);
        wsplit_kernel<<<g2, block>>>(f1w2, c.wt_hi + OFF_F1W2, c.wt_lo + OFF_F1W2, 4 * D_, D_);
        wsplit_kernel<<<g1, block>>>(f2w1, c.wt_hi + OFF_F2W1, c.wt_lo + OFF_F2W1, D_, 4 * D_);
        wsplit_kernel<<<g2, block>>>(f2w2, c.wt_hi + OFF_F2W2, c.wt_lo + OFF_F2W2, 4 * D_, D_);
    }

    const int n4 = M_ * D_ / 4;

    // ---- self-attention ----
    asplit_kernel<<<(n4 + 255) / 256, 256>>>(x, c.a_hi, c.a_lo, n4);
    run_gemm(c.a_hi, c.a_lo, c, OFF_QW, qb, nullptr, c.qhi, c.qlo, M_, D_, D_, 0, 1);
    run_gemm(c.a_hi, c.a_lo, c, OFF_KW, kb, nullptr, c.khi, c.klo, M_, D_, D_, 0, 1);
    run_gemm(c.a_hi, c.a_lo, c, OFF_VW, vb, nullptr, c.vhi, c.vlo, M_, D_, D_, 0, 1);
    run_attn(c, c.bms, c.b_hi, c.b_lo, 1);
    run_gemm(c.b_hi, c.b_lo, c, OFF_OW, ob, nullptr, c.a_hi, c.a_lo, M_, D_, D_, 0, 1);

    // ---- feedforward1 + norm1 ----
    run_gemm(c.a_hi, c.a_lo, c, OFF_F1W1, f1b1, nullptr, c.b_hi, c.b_lo, M_, 4*D_, D_, 1, 1);
    run_gemm(c.b_hi, c.b_lo, c, OFF_F1W2, f1b2, c.h2, nullptr, nullptr, M_, D_, 4*D_, 0, 0);
    layernorm_kernel<<<M_, 256>>>(c.h2, ln1g, ln1b, nullptr, c.a_hi, c.a_lo, 1);

    // ---- cross-attention ----
    run_gemm(c.a_hi, c.a_lo, c, OFF_CQW, nullptr, nullptr, c.qhi, c.qlo, M_, D_, D_, 0, 1);
    asplit_kernel<<<(n4 + 255) / 256, 256>>>(y, c.a_hi, c.a_lo, n4);
    run_gemm(c.a_hi, c.a_lo, c, OFF_CKW, nullptr, nullptr, c.khi, c.klo, M_, D_, D_, 0, 1);
    run_gemm(c.a_hi, c.a_lo, c, OFF_CVW, nullptr, nullptr, c.vhi, c.vlo, M_, D_, D_, 0, 1);
    run_attn(c, c.bmc, c.b_hi, c.b_lo, 0);
    run_gemm(c.b_hi, c.b_lo, c, OFF_COW, cob, nullptr, c.a_hi, c.a_lo, M_, D_, D_, 0, 1);

    // ---- feedforward2 + norm2 ----
    run_gemm(c.a_hi, c.a_lo, c, OFF_F2W1, f2b1, nullptr, c.b_hi, c.b_lo, M_, 4*D_, D_, 1, 1);
    run_gemm(c.b_hi, c.b_lo, c, OFF_F2W2, f2b2, c.h2, nullptr, nullptr, M_, D_, 4*D_, 0, 0);
    layernorm_kernel<<<M_, 256>>>(c.h2, ln2g, ln2b, out, nullptr, nullptr, 0);
}

// round 6
// speedup vs baseline: 5.2801x; 1.3599x over previous
#include <cuda_runtime.h>
#include <cuda_fp16.h>
#include <math.h>
#include <stdint.h>

// ---------------- problem constants ----------------
constexpr int B_ = 2;
constexpr int S_ = 2048;
constexpr int D_ = 1024;
constexpr int H_ = 16;
constexpr int HD_ = 64;
constexpr int M_ = B_ * S_;          // 4096 rows
constexpr float LN_EPS = 1e-5f;
constexpr int BM_WORDS = M_ * S_ / 32;

// ---------------- device scratch (no allocations allowed) ----------------
__device__ float g_h2 [M_ * D_];

constexpr size_t WT_ELEMS = 24ull * 1024 * 1024;
__device__ __half g_wt  [WT_ELEMS];                 // transposed weights, fp16 hi only
__device__ __half g_a_hi[M_ * 4 * D_];
__device__ __half g_a_lo[M_ * 4 * D_];
__device__ __half g_b_hi[M_ * 4 * D_];
__device__ __half g_b_lo[M_ * 4 * D_];
__device__ __half g_qhi[M_ * D_], g_qlo[M_ * D_];
__device__ __half g_khi[M_ * D_];                   // K hi only
__device__ __half g_vhi[M_ * D_];                   // V hi only
__device__ uint32_t g_bms[BM_WORDS];
__device__ uint32_t g_bmc[BM_WORDS];

// ---------------- PTX helpers (sm_80-class only) ----------------
__device__ __forceinline__ uint32_t smem_to_u32(const void* smem_ptr) {
    uint32_t addr;
    asm("{ .reg .u64 tmp; cvta.to.shared.u64 tmp, %1; cvt.u32.u64 %0, tmp; }"
        : "=r"(addr) : "l"(smem_ptr));
    return addr;
}
#define CP_ASYNC16(dst_u32, src_ptr) \
    asm volatile("cp.async.cg.shared.global [%0], [%1], 16;" \
        :: "r"(dst_u32), "l"(src_ptr))
#define CP_COMMIT() asm volatile("cp.async.commit_group;" ::: "memory")
#define CP_WAIT0()  asm volatile("cp.async.wait_group 0;" ::: "memory")
#define CP_WAIT1()  asm volatile("cp.async.wait_group 1;" ::: "memory")
#define CP_WAIT2()  asm volatile("cp.async.wait_group 2;" ::: "memory")
#define CP_WAIT3()  asm volatile("cp.async.wait_group 3;" ::: "memory")

#define LDSM_X4(r0, r1, r2, r3, addr) \
    asm volatile("ldmatrix.sync.aligned.m8n8.x4.shared.b16 {%0,%1,%2,%3}, [%4];" \
        : "=r"(r0), "=r"(r1), "=r"(r2), "=r"(r3) : "r"(addr))
#define LDSM_X4_T(r0, r1, r2, r3, addr) \
    asm volatile("ldmatrix.sync.aligned.m8n8.x4.trans.shared.b16 {%0,%1,%2,%3}, [%4];" \
        : "=r"(r0), "=r"(r1), "=r"(r2), "=r"(r3) : "r"(addr))

#define MMA_F16(c0, c1, c2, c3, a0, a1, a2, a3, b0, b1) \
    asm volatile("mma.sync.aligned.m16n8k16.row.col.f32.f16.f16.f32 " \
        "{%0,%1,%2,%3}, {%4,%5,%6,%7}, {%8,%9}, {%0,%1,%2,%3};" \
        : "+f"(c0), "+f"(c1), "+f"(c2), "+f"(c3) \
        : "r"(a0), "r"(a1), "r"(a2), "r"(a3), "r"(b0), "r"(b1))

__device__ __forceinline__ uint32_t h2u(__half2 v) {
    return *reinterpret_cast<uint32_t*>(&v);
}

// ============================================================
// HMMA fp16 GEMM: C = (Ah+Al)[M,K] @ Wh[N,K]^T   (2 MMA terms)
// CTA 128x128, BK=32, 8 warps (32x64), 4-stage cp.async.
// ============================================================
constexpr int TILEB   = 8192;                // one 128x32 fp16 tile
constexpr int STAGEB  = 3 * TILEB;           // Ah, Al, Wh = 24KB
constexpr int NSTAGE  = 4;
constexpr int GEMM_SMEM = NSTAGE * STAGEB;   // 98304

__device__ __forceinline__ uint32_t swz(uint32_t row, uint32_t gk) {
    return row * 64u + ((gk ^ ((row >> 1) & 3u)) << 4);
}

__global__ __launch_bounds__(256, 1)
void mma_gemm_kernel(const __half* __restrict__ Ahi, const __half* __restrict__ Alo,
                     const __half* __restrict__ Wh,
                     const float* __restrict__ bias, float* __restrict__ Cf,
                     __half* __restrict__ Chi, __half* __restrict__ Clo,
                     int M, int N, int K, int relu, int outmode)
{
    extern __shared__ char smem[];
    const uint32_t su = smem_to_u32(smem);
    const int tid  = threadIdx.x;
    const int wid  = tid >> 5;
    const int lane = tid & 31;
    const int block_row = blockIdx.y * 128;
    const int block_col = blockIdx.x * 128;

    const __half* basep[3] = { Ahi, Alo, Wh };
    const int rowoff[3] = { block_row, block_row, block_col };

    // 3 tiles x 512 chunks = 1536 / 256 threads = 6 chunks per thread
    auto load_stage = [&](int p, int kt) {
        const int k0 = kt * 32;
        #pragma unroll
        for (int i = 0; i < 6; i++) {
            int lin  = tid + (i << 8);
            int tile = lin >> 9;
            int rem  = lin & 511;
            int row  = rem >> 2;
            int g    = rem & 3;
            const __half* src =
                basep[tile] + (size_t)(rowoff[tile] + row) * K + k0 + g * 8;
            uint32_t dst = su + p * STAGEB + tile * TILEB + swz(row, g);
            CP_ASYNC16(dst, src);
        }
    };

    float c[2][8][4];
    #pragma unroll
    for (int s = 0; s < 2; s++)
        #pragma unroll
        for (int n = 0; n < 8; n++)
            #pragma unroll
            for (int i = 0; i < 4; i++) c[s][n][i] = 0.f;

    const int wm = (wid & 3) * 32;
    const int wn = (wid >> 2) * 64;

    const int a_row  = (lane & 15);
    const int a_gsel = (lane >> 4);
    const int b_noff = ((lane >> 4) << 3) + (lane & 7);
    const int b_gsel = (lane >> 3) & 1;

    const int KT = K >> 5;
    load_stage(0, 0); CP_COMMIT();
    load_stage(1, 1); CP_COMMIT();
    load_stage(2, 2); CP_COMMIT();

    for (int kt = 0; kt < KT; kt++) {
        if (kt + 3 < KT) { load_stage((kt + 3) & 3, kt + 3); CP_COMMIT(); }
        const int ahead = KT - 1 - kt;
        if (ahead >= 3)      CP_WAIT3();
        else if (ahead == 2) CP_WAIT2();
        else if (ahead == 1) CP_WAIT1();
        else                 CP_WAIT0();
        __syncthreads();

        const uint32_t stAhi = su + (kt & 3) * STAGEB;
        const uint32_t stAlo = stAhi + TILEB;
        const uint32_t stWh  = stAhi + 2 * TILEB;

        #pragma unroll
        for (int kk = 0; kk < 2; kk++) {
            uint32_t ah[2][4], al[2][4], bh[8][2];
            #pragma unroll
            for (int s = 0; s < 2; s++) {
                uint32_t ro = (uint32_t)(wm + s * 16 + a_row);
                uint32_t gk = (uint32_t)(kk * 2 + a_gsel);
                LDSM_X4(ah[s][0], ah[s][1], ah[s][2], ah[s][3], stAhi + swz(ro, gk));
                LDSM_X4(al[s][0], al[s][1], al[s][2], al[s][3], stAlo + swz(ro, gk));
            }
            #pragma unroll
            for (int grp = 0; grp < 4; grp++) {
                uint32_t ro = (uint32_t)(wn + grp * 16 + b_noff);
                uint32_t gk = (uint32_t)(kk * 2 + b_gsel);
                LDSM_X4(bh[2*grp][0], bh[2*grp][1], bh[2*grp+1][0], bh[2*grp+1][1],
                        stWh + swz(ro, gk));
            }
            #pragma unroll
            for (int s = 0; s < 2; s++)
                #pragma unroll
                for (int n = 0; n < 8; n++)
                    MMA_F16(c[s][n][0], c[s][n][1], c[s][n][2], c[s][n][3],
                            ah[s][0], ah[s][1], ah[s][2], ah[s][3],
                            bh[n][0], bh[n][1]);
            #pragma unroll
            for (int s = 0; s < 2; s++)
                #pragma unroll
                for (int n = 0; n < 8; n++)
                    MMA_F16(c[s][n][0], c[s][n][1], c[s][n][2], c[s][n][3],
                            al[s][0], al[s][1], al[s][2], al[s][3],
                            bh[n][0], bh[n][1]);
        }
        __syncthreads();
    }

    const int gp  = lane >> 2;
    const int tig = lane & 3;
    #pragma unroll
    for (int s = 0; s < 2; s++) {
        const int r0 = block_row + wm + s * 16 + gp;
        #pragma unroll
        for (int n = 0; n < 8; n++) {
            const int col = block_col + wn + n * 8 + tig * 2;
            float b0 = bias ? __ldg(&bias[col])     : 0.f;
            float b1 = bias ? __ldg(&bias[col + 1]) : 0.f;
            float v0 = c[s][n][0] + b0, v1 = c[s][n][1] + b1;
            float v2 = c[s][n][2] + b0, v3 = c[s][n][3] + b1;
            if (relu) {
                v0 = fmaxf(v0, 0.f); v1 = fmaxf(v1, 0.f);
                v2 = fmaxf(v2, 0.f); v3 = fmaxf(v3, 0.f);
            }
            if (outmode == 0) {
                *(float2*)&Cf[(size_t)r0 * N + col]       = make_float2(v0, v1);
                *(float2*)&Cf[(size_t)(r0 + 8) * N + col] = make_float2(v2, v3);
            } else {
                __half2 h01 = __float22half2_rn(make_float2(v0, v1));
                __half2 h23 = __float22half2_rn(make_float2(v2, v3));
                *(__half2*)&Chi[(size_t)r0 * N + col]       = h01;
                *(__half2*)&Chi[(size_t)(r0 + 8) * N + col] = h23;
                if (outmode == 1) {
                    __half2 l01 = __float22half2_rn(make_float2(
                        v0 - __half2float(h01.x), v1 - __half2float(h01.y)));
                    __half2 l23 = __float22half2_rn(make_float2(
                        v2 - __half2float(h23.x), v3 - __half2float(h23.y)));
                    *(__half2*)&Clo[(size_t)r0 * N + col]       = l01;
                    *(__half2*)&Clo[(size_t)(r0 + 8) * N + col] = l23;
                }
            }
        }
    }
}

// ============================================================
// MMA flash attention (fp16, 2-term). K/V hi only, bitmap mask,
// double-buffered. CTA: 64 q-rows, 4 warps, Bc=64.
// ============================================================
constexpr int ATT_STAGE = 16384;             // Kh, Vh tiles (8KB each)
constexpr int ATT_SMEM  = 2 * ATT_STAGE;     // 32768

__device__ __forceinline__ uint32_t offKV(uint32_t row, uint32_t g) {
    return row * 128u + ((g ^ (row & 7u)) << 4);
}

__global__ __launch_bounds__(128)
void mma_attn_kernel(const __half* __restrict__ Qhi, const __half* __restrict__ Qlo,
                     const __half* __restrict__ Khi, const __half* __restrict__ Vhi,
                     const uint32_t* __restrict__ bm,
                     __half* __restrict__ Ohi, __half* __restrict__ Olo,
                     int selfmode)
{
    extern __shared__ char smem[];
    const uint32_t su = smem_to_u32(smem);
    const int tid = threadIdx.x, wid = tid >> 5, lane = tid & 31;
    const int b = blockIdx.x >> 4, h = blockIdx.x & 15;
    const int q0 = blockIdx.y * 64;

    // ---- stage Q hi/lo tiles, build A fragments ----
    #pragma unroll
    for (int i = 0; i < 8; i++) {
        int lin = tid + (i << 7);
        int t = lin >> 9, rem = lin & 511, row = rem >> 3, g = rem & 7;
        const __half* src = (t ? Qlo : Qhi) +
            ((size_t)b * S_ + q0 + row) * D_ + h * 64 + g * 8;
        CP_ASYNC16(su + t * 8192 + offKV(row, g), src);
    }
    CP_COMMIT(); CP_WAIT0(); __syncthreads();

    uint32_t qa_hi[4][4], qa_lo[4][4];
    {
        const uint32_t arow = (uint32_t)(wid * 16 + (lane & 15));
        const uint32_t ag = (uint32_t)(lane >> 4);
        #pragma unroll
        for (int kk = 0; kk < 4; kk++) {
            LDSM_X4(qa_hi[kk][0], qa_hi[kk][1], qa_hi[kk][2], qa_hi[kk][3],
                    su + offKV(arow, kk * 2 + ag));
            LDSM_X4(qa_lo[kk][0], qa_lo[kk][1], qa_lo[kk][2], qa_lo[kk][3],
                    su + 8192 + offKV(arow, kk * 2 + ag));
        }
    }
    __syncthreads();

    float o[8][4];
    #pragma unroll
    for (int n = 0; n < 8; n++)
        #pragma unroll
        for (int i = 0; i < 4; i++) o[n][i] = 0.f;
    float m0 = -INFINITY, m1 = -INFINITY, l0 = 0.f, l1 = 0.f;
    const float scale = 0.125f;
    const float bigneg = selfmode ? -3.0e38f : -1.25e8f;

    const int b_noff = ((lane >> 4) << 3) + (lane & 7);
    const int b_gsel = (lane >> 3) & 1;
    const int mr0 = wid * 16 + (lane >> 2);
    const int msh = (2 * (lane & 3));

    const __half* kvp[2] = { Khi, Vhi };
    const uint32_t* bmr0 = bm + ((size_t)b * S_ + q0 + mr0) * (S_ / 32);
    const uint32_t* bmr1 = bmr0 + 8 * (S_ / 32);

    auto load_kv = [&](int buf, int jt) {
        const int j0 = jt * 64;
        #pragma unroll
        for (int i = 0; i < 8; i++) {
            int lin = tid + (i << 7);
            int t = lin >> 9, rem = lin & 511, row = rem >> 3, g = rem & 7;
            CP_ASYNC16(su + buf * ATT_STAGE + t * 8192 + offKV(row, g),
                       kvp[t] + ((size_t)b * S_ + j0 + row) * D_ + h * 64 + g * 8);
        }
    };

    load_kv(0, 0); CP_COMMIT();

    for (int jt = 0; jt < 32; jt++) {
        if (jt + 1 < 32) { load_kv((jt + 1) & 1, jt + 1); CP_COMMIT(); CP_WAIT1(); }
        else             { CP_WAIT0(); }
        __syncthreads();

        const uint32_t sb = su + (jt & 1) * ATT_STAGE;

        const uint32_t u00 = __ldg(&bmr0[jt * 2]), u01 = __ldg(&bmr0[jt * 2 + 1]);
        const uint32_t u10 = __ldg(&bmr1[jt * 2]), u11 = __ldg(&bmr1[jt * 2 + 1]);

        // ---- S = Q K^T (2-term: Qh*Kh + Ql*Kh) ----
        float sc[8][4];
        #pragma unroll
        for (int n = 0; n < 8; n++)
            #pragma unroll
            for (int i = 0; i < 4; i++) sc[n][i] = 0.f;

        #pragma unroll
        for (int kk = 0; kk < 4; kk++) {
            uint32_t kbh[8][2];
            #pragma unroll
            for (int grp = 0; grp < 4; grp++) {
                uint32_t ro = (uint32_t)(grp * 16 + b_noff);
                uint32_t gd = (uint32_t)(kk * 2 + b_gsel);
                LDSM_X4(kbh[2*grp][0], kbh[2*grp][1], kbh[2*grp+1][0], kbh[2*grp+1][1],
                        sb + offKV(ro, gd));
            }
            #pragma unroll
            for (int n = 0; n < 8; n++)
                MMA_F16(sc[n][0], sc[n][1], sc[n][2], sc[n][3],
                        qa_hi[kk][0], qa_hi[kk][1], qa_hi[kk][2], qa_hi[kk][3],
                        kbh[n][0], kbh[n][1]);
            #pragma unroll
            for (int n = 0; n < 8; n++)
                MMA_F16(sc[n][0], sc[n][1], sc[n][2], sc[n][3],
                        qa_lo[kk][0], qa_lo[kk][1], qa_lo[kk][2], qa_lo[kk][3],
                        kbh[n][0], kbh[n][1]);
        }

        // ---- mask + scale ----
        #pragma unroll
        for (int n = 0; n < 8; n++) {
            const uint32_t w0 = (n < 4) ? u00 : u01;
            const uint32_t w1 = (n < 4) ? u10 : u11;
            const int sh = ((n * 8) & 31) + msh;
            bool f0 = (w0 >> sh) & 1, f1 = (w0 >> (sh + 1)) & 1;
            bool f2 = (w1 >> sh) & 1, f3 = (w1 >> (sh + 1)) & 1;
            sc[n][0] = f0 ? bigneg : sc[n][0] * scale;
            sc[n][1] = f1 ? bigneg : sc[n][1] * scale;
            sc[n][2] = f2 ? bigneg : sc[n][2] * scale;
            sc[n][3] = f3 ? bigneg : sc[n][3] * scale;
        }

        // ---- online softmax ----
        float tm0 = -INFINITY, tm1 = -INFINITY;
        #pragma unroll
        for (int n = 0; n < 8; n++) {
            tm0 = fmaxf(tm0, fmaxf(sc[n][0], sc[n][1]));
            tm1 = fmaxf(tm1, fmaxf(sc[n][2], sc[n][3]));
        }
        tm0 = fmaxf(tm0, __shfl_xor_sync(0xffffffffu, tm0, 1));
        tm0 = fmaxf(tm0, __shfl_xor_sync(0xffffffffu, tm0, 2));
        tm1 = fmaxf(tm1, __shfl_xor_sync(0xffffffffu, tm1, 1));
        tm1 = fmaxf(tm1, __shfl_xor_sync(0xffffffffu, tm1, 2));
        float nm0 = fmaxf(m0, tm0), nm1 = fmaxf(m1, tm1);
        float c0 = __expf(m0 - nm0), c1 = __expf(m1 - nm1);
        m0 = nm0; m1 = nm1;

        float rs0 = 0.f, rs1 = 0.f;
        uint32_t pah[8][2], pal[8][2];
        #pragma unroll
        for (int n = 0; n < 8; n++) {
            float p0 = __expf(sc[n][0] - m0);
            float p1 = __expf(sc[n][1] - m0);
            float p2 = __expf(sc[n][2] - m1);
            float p3 = __expf(sc[n][3] - m1);
            rs0 += p0 + p1; rs1 += p2 + p3;
            __half2 h01 = __float22half2_rn(make_float2(p0, p1));
            __half2 h23 = __float22half2_rn(make_float2(p2, p3));
            pah[n][0] = h2u(h01); pah[n][1] = h2u(h23);
            __half2 q01 = __float22half2_rn(make_float2(
                p0 - __half2float(h01.x), p1 - __half2float(h01.y)));
            __half2 q23 = __float22half2_rn(make_float2(
                p2 - __half2float(h23.x), p3 - __half2float(h23.y)));
            pal[n][0] = h2u(q01); pal[n][1] = h2u(q23);
        }
        rs0 += __shfl_xor_sync(0xffffffffu, rs0, 1);
        rs0 += __shfl_xor_sync(0xffffffffu, rs0, 2);
        rs1 += __shfl_xor_sync(0xffffffffu, rs1, 1);
        rs1 += __shfl_xor_sync(0xffffffffu, rs1, 2);
        l0 = l0 * c0 + rs0;
        l1 = l1 * c1 + rs1;
        #pragma unroll
        for (int n = 0; n < 8; n++) {
            o[n][0] *= c0; o[n][1] *= c0; o[n][2] *= c1; o[n][3] *= c1;
        }

        // ---- O += P V (2-term: Ph*Vh + Pl*Vh) ----
        #pragma unroll
        for (int kk = 0; kk < 4; kk++) {
            uint32_t ah0 = pah[2*kk][0], ah1 = pah[2*kk][1];
            uint32_t ah2 = pah[2*kk+1][0], ah3 = pah[2*kk+1][1];
            uint32_t al0 = pal[2*kk][0], al1 = pal[2*kk][1];
            uint32_t al2 = pal[2*kk+1][0], al3 = pal[2*kk+1][1];
            uint32_t vrow = (uint32_t)(kk * 16 + (lane & 15));
            #pragma unroll
            for (int nbp = 0; nbp < 4; nbp++) {
                uint32_t vg = (uint32_t)(nbp * 2 + (lane >> 4));
                uint32_t vh0, vh1, vh2, vh3;
                LDSM_X4_T(vh0, vh1, vh2, vh3, sb + 8192 + offKV(vrow, vg));
                MMA_F16(o[2*nbp][0], o[2*nbp][1], o[2*nbp][2], o[2*nbp][3],
                        ah0, ah1, ah2, ah3, vh0, vh1);
                MMA_F16(o[2*nbp+1][0], o[2*nbp+1][1], o[2*nbp+1][2], o[2*nbp+1][3],
                        ah0, ah1, ah2, ah3, vh2, vh3);
                MMA_F16(o[2*nbp][0], o[2*nbp][1], o[2*nbp][2], o[2*nbp][3],
                        al0, al1, al2, al3, vh0, vh1);
                MMA_F16(o[2*nbp+1][0], o[2*nbp+1][1], o[2*nbp+1][2], o[2*nbp+1][3],
                        al0, al1, al2, al3, vh2, vh3);
            }
        }
        __syncthreads();
    }

    // ---- epilogue: normalize, split to fp16 hi/lo ----
    const float i0 = 1.f / l0, i1 = 1.f / l1;
    const size_t gr0 = (size_t)b * S_ + q0 + wid * 16 + (lane >> 2);
    #pragma unroll
    for (int n = 0; n < 8; n++) {
        const int col = h * 64 + n * 8 + 2 * (lane & 3);
        float v0 = o[n][0] * i0, v1 = o[n][1] * i0;
        float v2 = o[n][2] * i1, v3 = o[n][3] * i1;
        __half2 h01 = __float22half2_rn(make_float2(v0, v1));
        __half2 h23 = __float22half2_rn(make_float2(v2, v3));
        __half2 l01 = __float22half2_rn(make_float2(
            v0 - __half2float(h01.x), v1 - __half2float(h01.y)));
        __half2 l23 = __float22half2_rn(make_float2(
            v2 - __half2float(h23.x), v3 - __half2float(h23.y)));
        *(__half2*)&Ohi[gr0 * D_ + col]       = h01;
        *(__half2*)&Ohi[(gr0 + 8) * D_ + col] = h23;
        *(__half2*)&Olo[gr0 * D_ + col]       = l01;
        *(__half2*)&Olo[(gr0 + 8) * D_ + col] = l23;
    }
}

// ============================================================
// prep kernels
// ============================================================
__global__ __launch_bounds__(256)
void mprep_kernel(const int* __restrict__ mask, uint32_t* __restrict__ bms,
                  uint32_t* __restrict__ bmc)
{
    const int lane = threadIdx.x & 31;
    const size_t w = ((size_t)blockIdx.x * blockDim.x + threadIdx.x) >> 5;
    const size_t base = w * 1024;
    #pragma unroll 4
    for (int i = 0; i < 32; i++) {
        int mv = mask[base + i * 32 + lane];
        uint32_t s = __ballot_sync(0xffffffffu, mv == 1);
        uint32_t c = __ballot_sync(0xffffffffu, mv != 0);
        if (lane == 0) { bms[w * 32 + i] = s; bmc[w * 32 + i] = c; }
    }
}

// transpose + fp16 convert (hi only): W[K,N] -> Wt[N,K]
struct WB8 { const float* src[8]; __half* dst[8]; };
__global__ __launch_bounds__(256)
void wsplit8_kernel(WB8 p)
{
    __shared__ float t[32][33];
    const int tx = threadIdx.x, ty = threadIdx.y;
    const int n0 = blockIdx.x * 32, k0 = blockIdx.y * 32;
    const float* W = p.src[blockIdx.z];
    __half* dst = p.dst[blockIdx.z];
    #pragma unroll
    for (int r = 0; r < 4; r++)
        t[ty + r * 8][tx] = W[(size_t)(k0 + ty + r * 8) * D_ + n0 + tx];
    __syncthreads();
    #pragma unroll
    for (int r = 0; r < 4; r++)
        dst[(size_t)(n0 + ty + r * 8) * D_ + k0 + tx] =
            __float2half_rn(t[tx][ty + r * 8]);
}

struct WB2 { const float* src[2]; __half* dst[2]; };
__global__ __launch_bounds__(256)
void wsplitF_kernel(WB2 p, int K, int N)
{
    __shared__ float t[32][33];
    const int tx = threadIdx.x, ty = threadIdx.y;
    const int n0 = blockIdx.x * 32, k0 = blockIdx.y * 32;
    const float* W = p.src[blockIdx.z];
    __half* dst = p.dst[blockIdx.z];
    #pragma unroll
    for (int r = 0; r < 4; r++)
        t[ty + r * 8][tx] = W[(size_t)(k0 + ty + r * 8) * N + n0 + tx];
    __syncthreads();
    #pragma unroll
    for (int r = 0; r < 4; r++)
        dst[(size_t)(n0 + ty + r * 8) * K + k0 + tx] =
            __float2half_rn(t[tx][ty + r * 8]);
}

// activation fp16 hi/lo split
__global__ __launch_bounds__(256)
void asplit_kernel(const float* __restrict__ A, __half* __restrict__ hi,
                   __half* __restrict__ lo, int n4)
{
    int i = blockIdx.x * 256 + threadIdx.x;
    if (i >= n4) return;
    float4 v = ((const float4*)A)[i];
    __half2 h01 = __float22half2_rn(make_float2(v.x, v.y));
    __half2 h23 = __float22half2_rn(make_float2(v.z, v.w));
    __half2 l01 = __float22half2_rn(make_float2(
        v.x - __half2float(h01.x), v.y - __half2float(h01.y)));
    __half2 l23 = __float22half2_rn(make_float2(
        v.z - __half2float(h23.x), v.w - __half2float(h23.y)));
    ((__half2*)hi)[2 * i + 0] = h01;
    ((__half2*)hi)[2 * i + 1] = h23;
    ((__half2*)lo)[2 * i + 0] = l01;
    ((__half2*)lo)[2 * i + 1] = l23;
}

// ============================================================
// LayerNorm
// ============================================================
__global__ __launch_bounds__(256)
void layernorm_kernel(const float* __restrict__ X, const float* __restrict__ gm,
                      const float* __restrict__ bt, float* __restrict__ Yf,
                      __half* __restrict__ Yhi, __half* __restrict__ Ylo,
                      int outmode)
{
    const int row = blockIdx.x;
    const int t = threadIdx.x;
    const float* x = X + (size_t)row * D_;

    float4 xv = *(const float4*)&x[t * 4];
    float s  = xv.x + xv.y + xv.z + xv.w;
    float ss = xv.x * xv.x + xv.y * xv.y + xv.z * xv.z + xv.w * xv.w;

    #pragma unroll
    for (int off = 16; off > 0; off >>= 1) {
        s  += __shfl_xor_sync(0xffffffffu, s, off);
        ss += __shfl_xor_sync(0xffffffffu, ss, off);
    }
    __shared__ float sbuf[8], ssbuf[8];
    if ((t & 31) == 0) { sbuf[t >> 5] = s; ssbuf[t >> 5] = ss; }
    __syncthreads();
    float ts = 0.f, tss = 0.f;
    #pragma unroll
    for (int i = 0; i < 8; i++) { ts += sbuf[i]; tss += ssbuf[i]; }

    const float invD = 1.f / (float)D_;
    float mu  = ts * invD;
    float var = tss * invD - mu * mu;
    float inv = rsqrtf(var + LN_EPS);

    float4 gv = *(const float4*)&gm[t * 4];
    float4 bv = *(const float4*)&bt[t * 4];
    float o0 = (xv.x - mu) * inv * gv.x + bv.x;
    float o1 = (xv.y - mu) * inv * gv.y + bv.y;
    float o2 = (xv.z - mu) * inv * gv.z + bv.z;
    float o3 = (xv.w - mu) * inv * gv.w + bv.w;

    if (outmode == 0) {
        *(float4*)&Yf[(size_t)row * D_ + t * 4] = make_float4(o0, o1, o2, o3);
    } else {
        __half2 h01 = __float22half2_rn(make_float2(o0, o1));
        __half2 h23 = __float22half2_rn(make_float2(o2, o3));
        __half2 l01 = __float22half2_rn(make_float2(
            o0 - __half2float(h01.x), o1 - __half2float(h01.y)));
        __half2 l23 = __float22half2_rn(make_float2(
            o2 - __half2float(h23.x), o3 - __half2float(h23.y)));
        *(__half2*)&Yhi[(size_t)row * D_ + t * 4]     = h01;
        *(__half2*)&Yhi[(size_t)row * D_ + t * 4 + 2] = h23;
        *(__half2*)&Ylo[(size_t)row * D_ + t * 4]     = l01;
        *(__half2*)&Ylo[(size_t)row * D_ + t * 4 + 2] = l23;
    }
}

// ============================================================
// launch plumbing
// ============================================================
constexpr size_t MB1 = 1024ull * 1024ull;
constexpr size_t OFF_QW = 0,       OFF_KW = 1*MB1,  OFF_VW = 2*MB1,  OFF_OW = 3*MB1;
constexpr size_t OFF_F1W1 = 4*MB1, OFF_F1W2 = 8*MB1;
constexpr size_t OFF_CQW = 12*MB1, OFF_CKW = 13*MB1, OFF_CVW = 14*MB1, OFF_COW = 15*MB1;
constexpr size_t OFF_F2W1 = 16*MB1, OFF_F2W2 = 20*MB1;

struct Ctx {
    __half *wt;
    __half *a_hi, *a_lo, *b_hi, *b_lo;
    __half *qhi, *qlo, *khi, *vhi;
    float *h2;
    uint32_t *bms, *bmc;
};

static inline void run_gemm(const __half* Ahi, const __half* Alo,
                            const Ctx& c, size_t woff, const float* bias,
                            float* Cf, __half* Chi, __half* Clo,
                            int M, int N, int K, int relu, int outmode) {
    dim3 grid(N / 128, M / 128), block(256);
    mma_gemm_kernel<<<grid, block, GEMM_SMEM>>>(
        Ahi, Alo, c.wt + woff, bias, Cf, Chi, Clo, M, N, K, relu, outmode);
}
static inline void run_attn(const Ctx& c, const uint32_t* bm,
                            __half* ohi, __half* olo, int selfmode) {
    dim3 grid(B_ * H_, S_ / 64), block(128);
    mma_attn_kernel<<<grid, block, ATT_SMEM>>>(
        c.qhi, c.qlo, c.khi, c.vhi, bm, ohi, olo, selfmode);
}

extern "C" void kernel_launch(void* const* d_in, const int* in_sizes, int n_in,
                              void* d_out, int out_size)
{
    (void)in_sizes; (void)n_in; (void)out_size;
    const float* x    = (const float*)d_in[0];
    const float* y    = (const float*)d_in[1];
    const int*   mask = (const int*)  d_in[2];
    const float* qw   = (const float*)d_in[3];
    const float* qb   = (const float*)d_in[4];
    const float* kw   = (const float*)d_in[5];
    const float* kb   = (const float*)d_in[6];
    const float* vw   = (const float*)d_in[7];
    const float* vb   = (const float*)d_in[8];
    const float* ow   = (const float*)d_in[9];
    const float* ob   = (const float*)d_in[10];
    const float* f1w1 = (const float*)d_in[11];
    const float* f1b1 = (const float*)d_in[12];
    const float* f1w2 = (const float*)d_in[13];
    const float* f1b2 = (const float*)d_in[14];
    const float* ln1g = (const float*)d_in[15];
    const float* ln1b = (const float*)d_in[16];
    const float* cqw  = (const float*)d_in[17];
    const float* ckw  = (const float*)d_in[18];
    const float* cvw  = (const float*)d_in[19];
    const float* cow  = (const float*)d_in[20];
    const float* cob  = (const float*)d_in[21];
    const float* f2w1 = (const float*)d_in[22];
    const float* f2b1 = (const float*)d_in[23];
    const float* f2w2 = (const float*)d_in[24];
    const float* f2b2 = (const float*)d_in[25];
    const float* ln2g = (const float*)d_in[26];
    const float* ln2b = (const float*)d_in[27];
    float* out = (float*)d_out;

    Ctx c;
    cudaGetSymbolAddress((void**)&c.wt,   g_wt);
    cudaGetSymbolAddress((void**)&c.a_hi, g_a_hi);
    cudaGetSymbolAddress((void**)&c.a_lo, g_a_lo);
    cudaGetSymbolAddress((void**)&c.b_hi, g_b_hi);
    cudaGetSymbolAddress((void**)&c.b_lo, g_b_lo);
    cudaGetSymbolAddress((void**)&c.qhi,  g_qhi);
    cudaGetSymbolAddress((void**)&c.qlo,  g_qlo);
    cudaGetSymbolAddress((void**)&c.khi,  g_khi);
    cudaGetSymbolAddress((void**)&c.vhi,  g_vhi);
    cudaGetSymbolAddress((void**)&c.h2,   g_h2);
    cudaGetSymbolAddress((void**)&c.bms,  g_bms);
    cudaGetSymbolAddress((void**)&c.bmc,  g_bmc);

    cudaFuncSetAttribute(mma_gemm_kernel,
                         cudaFuncAttributeMaxDynamicSharedMemorySize, GEMM_SMEM);
    cudaFuncSetAttribute(mma_attn_kernel,
                         cudaFuncAttributeMaxDynamicSharedMemorySize, ATT_SMEM);

    // ---- prep: exactly 5 launches before first GEMM (ncu -s 5 captures it) ----
    mprep_kernel<<<BM_WORDS / 32 / 8, 256>>>(mask, c.bms, c.bmc);   // 1
    {
        WB8 p;
        const float* srcs[8] = { qw, kw, vw, ow, cqw, ckw, cvw, cow };
        const size_t offs[8] = { OFF_QW, OFF_KW, OFF_VW, OFF_OW,
                                 OFF_CQW, OFF_CKW, OFF_CVW, OFF_COW };
        for (int i = 0; i < 8; i++) { p.src[i] = srcs[i]; p.dst[i] = c.wt + offs[i]; }
        dim3 grid(32, 32, 8), block(32, 8);
        wsplit8_kernel<<<grid, block>>>(p);                         // 2
    }
    {
        dim3 block(32, 8);
        WB2 p1; p1.src[0] = f1w1; p1.src[1] = f2w1;
        p1.dst[0] = c.wt + OFF_F1W1; p1.dst[1] = c.wt + OFF_F2W1;
        wsplitF_kernel<<<dim3(128, 32, 2), block>>>(p1, D_, 4 * D_);  // 3
        WB2 p2; p2.src[0] = f1w2; p2.src[1] = f2w2;
        p2.dst[0] = c.wt + OFF_F1W2; p2.dst[1] = c.wt + OFF_F2W2;
        wsplitF_kernel<<<dim3(32, 128, 2), block>>>(p2, 4 * D_, D_);  // 4
    }
    const int n4 = M_ * D_ / 4;
    asplit_kernel<<<(n4 + 255) / 256, 256>>>(x, c.a_hi, c.a_lo, n4);  // 5

    // ---- self-attention ----
    run_gemm(c.a_hi, c.a_lo, c, OFF_QW, qb, nullptr, c.qhi, c.qlo, M_, D_, D_, 0, 1);
    run_gemm(c.a_hi, c.a_lo, c, OFF_KW, kb, nullptr, c.khi, nullptr, M_, D_, D_, 0, 2);
    run_gemm(c.a_hi, c.a_lo, c, OFF_VW, vb, nullptr, c.vhi, nullptr, M_, D_, D_, 0, 2);
    run_attn(c, c.bms, c.b_hi, c.b_lo, 1);
    run_gemm(c.b_hi, c.b_lo, c, OFF_OW, ob, nullptr, c.a_hi, c.a_lo, M_, D_, D_, 0, 1);

    // ---- feedforward1 + norm1 ----
    run_gemm(c.a_hi, c.a_lo, c, OFF_F1W1, f1b1, nullptr, c.b_hi, c.b_lo, M_, 4*D_, D_, 1, 1);
    run_gemm(c.b_hi, c.b_lo, c, OFF_F1W2, f1b2, c.h2, nullptr, nullptr, M_, D_, 4*D_, 0, 0);
    layernorm_kernel<<<M_, 256>>>(c.h2, ln1g, ln1b, nullptr, c.a_hi, c.a_lo, 1);

    // ---- cross-attention ----
    run_gemm(c.a_hi, c.a_lo, c, OFF_CQW, nullptr, nullptr, c.qhi, c.qlo, M_, D_, D_, 0, 1);
    asplit_kernel<<<(n4 + 255) / 256, 256>>>(y, c.a_hi, c.a_lo, n4);
    run_gemm(c.a_hi, c.a_lo, c, OFF_CKW, nullptr, nullptr, c.khi, nullptr, M_, D_, D_, 0, 2);
    run_gemm(c.a_hi, c.a_lo, c, OFF_CVW, nullptr, nullptr, c.vhi, nullptr, M_, D_, D_, 0, 2);
    run_attn(c, c.bmc, c.b_hi, c.b_lo, 0);
    run_gemm(c.b_hi, c.b_lo, c, OFF_COW, cob, nullptr, c.a_hi, c.a_lo, M_, D_, D_, 0, 1);

    // ---- feedforward2 + norm2 ----
    run_gemm(c.a_hi, c.a_lo, c, OFF_F2W1, f2b1, nullptr, c.b_hi, c.b_lo, M_, 4*D_, D_, 1, 1);
    run_gemm(c.b_hi, c.b_lo, c, OFF_F2W2, f2b2, c.h2, nullptr, nullptr, M_, D_, 4*D_, 0, 0);
    layernorm_kernel<<<M_, 256>>>(c.h2, ln2g, ln2b, out, nullptr, nullptr, 0);
}